// round 9
// baseline (speedup 1.0000x reference)
#include <cuda_runtime.h>
#include <cuda_fp16.h>
#include <cstdint>

#define C_DIM   768
#define QKV_DIM 3072
#define BATCH   4
#define SEQ     1024
#define HEADS   12
#define HD      64
#define M_ROWS  (BATCH*SEQ)   // 4096

// -------- scratch (allocation-free: device globals) --------
__device__ float g_qkv_x[M_ROWS*QKV_DIM];
__device__ float g_qkv_y[M_ROWS*QKV_DIM];
__device__ float g_att_x[M_ROWS*C_DIM];
__device__ float g_att_y[M_ROWS*C_DIM];
__device__ __half g_x_hi[M_ROWS*C_DIM],     g_x_lo[M_ROWS*C_DIM];
__device__ __half g_y_hi[M_ROWS*C_DIM],     g_y_lo[M_ROWS*C_DIM];
__device__ __half g_wqkv_hi[QKV_DIM*C_DIM], g_wqkv_lo[QKV_DIM*C_DIM];
__device__ __half g_wproj_hi[C_DIM*C_DIM],  g_wproj_lo[C_DIM*C_DIM];
__device__ __half g_ax_hi[M_ROWS*C_DIM],    g_ax_lo[M_ROWS*C_DIM];
__device__ __half g_ay_hi[M_ROWS*C_DIM],    g_ay_lo[M_ROWS*C_DIM];

// ============================================================
// helpers
// ============================================================
__device__ __forceinline__ uint32_t smem_u32(const void* p) {
    uint32_t a;
    asm("{ .reg .u64 t; cvta.to.shared.u64 t, %1; cvt.u32.u64 %0, t; }"
        : "=r"(a) : "l"(p));
    return a;
}

__device__ __forceinline__ void ldsm_x4(uint32_t addr, uint32_t& r0, uint32_t& r1,
                                        uint32_t& r2, uint32_t& r3) {
    asm volatile("ldmatrix.sync.aligned.m8n8.x4.shared.b16 {%0,%1,%2,%3}, [%4];"
                 : "=r"(r0), "=r"(r1), "=r"(r2), "=r"(r3) : "r"(addr));
}

__device__ __forceinline__ void mma_f16(float* c, const uint32_t* a,
                                        uint32_t b0, uint32_t b1) {
    asm volatile(
        "mma.sync.aligned.m16n8k16.row.col.f32.f16.f16.f32 "
        "{%0,%1,%2,%3}, {%4,%5,%6,%7}, {%8,%9}, {%0,%1,%2,%3};"
        : "+f"(c[0]), "+f"(c[1]), "+f"(c[2]), "+f"(c[3])
        : "r"(a[0]), "r"(a[1]), "r"(a[2]), "r"(a[3]), "r"(b0), "r"(b1));
}

__device__ __forceinline__ void cp_async16(uint32_t saddr, const void* gptr) {
    asm volatile("cp.async.cg.shared.global [%0], [%1], 16;"
                 :: "r"(saddr), "l"(gptr));
}
__device__ __forceinline__ void cp_commit() {
    asm volatile("cp.async.commit_group;" ::: "memory");
}
__device__ __forceinline__ void cp_wait0() { asm volatile("cp.async.wait_group 0;" ::: "memory"); }
__device__ __forceinline__ void cp_wait1() { asm volatile("cp.async.wait_group 1;" ::: "memory"); }
__device__ __forceinline__ void cp_wait2() { asm volatile("cp.async.wait_group 2;" ::: "memory"); }

__device__ __forceinline__ uint32_t pack_h2(__half a, __half b) {
    return ((uint32_t)__half_as_ushort(b) << 16) | (uint32_t)__half_as_ushort(a);
}

// split fp32 float4 -> hi/lo fp16 limb pairs
__device__ __forceinline__ void split4h(float4 v, uint2& hi, uint2& lo) {
    __half h0 = __float2half_rn(v.x);
    __half h1 = __float2half_rn(v.y);
    __half h2 = __float2half_rn(v.z);
    __half h3 = __float2half_rn(v.w);
    __half l0 = __float2half_rn(v.x - __half2float(h0));
    __half l1 = __float2half_rn(v.y - __half2float(h1));
    __half l2 = __float2half_rn(v.z - __half2float(h2));
    __half l3 = __float2half_rn(v.w - __half2float(h3));
    hi.x = pack_h2(h0, h1); hi.y = pack_h2(h2, h3);
    lo.x = pack_h2(l0, l1); lo.y = pack_h2(l2, l3);
}

// fp32 float4 -> fp16 hi only
__device__ __forceinline__ uint2 hi4h(float4 v) {
    return make_uint2(pack_h2(__float2half_rn(v.x), __float2half_rn(v.y)),
                      pack_h2(__float2half_rn(v.z), __float2half_rn(v.w)));
}

// ============================================================
// fp32 -> fp16 limb split kernel (memory-bound pre-pass)
// ============================================================
__global__ __launch_bounds__(256) void split_kernel(
    const float* __restrict__ src, __half* __restrict__ hi,
    __half* __restrict__ lo, int n4)
{
    int i = blockIdx.x * 256 + threadIdx.x;
    if (i < n4) {
        float4 v = ((const float4*)src)[i];
        uint2 h, l;
        split4h(v, h, l);
        ((uint2*)hi)[i] = h;
        ((uint2*)lo)[i] = l;
    }
}

// ============================================================
// split-fp16 mma.sync GEMM, limb inputs. 2-pass: AhBh + AlBh.
// CTA tile 128m x 256n, 8 warps (2m x 4n), warp tile 64x64.
// BK=16, 4-deep cp.async ring, 1 sync/stage.
// ============================================================
#define LDH2 24                        // halves per row (16 + 8 pad)
#define ACH  (128 * LDH2)              // 3072 halves per A limb array
#define BCH  (256 * LDH2)              // 6144 halves per B array
#define STGH2 (2*ACH + BCH)            // 12288 halves per stage
#define STGB  (STGH2 * 2)              // 24576 bytes per stage
#define GEMM_SMEM (4 * STGB)           // 98304

__global__ __launch_bounds__(256, 1) void gemm_mma(
    const __half* __restrict__ Ah0, const __half* __restrict__ Al0,
    const __half* __restrict__ Ah1, const __half* __restrict__ Al1,
    const __half* __restrict__ Bh,
    const float* __restrict__ bias,
    float* __restrict__ C0, float* __restrict__ C1,
    int M, int N, int K, int n_lim1)
{
    extern __shared__ __align__(16) __half sh[];
    const int tid  = threadIdx.x;
    const int wid  = tid >> 5;
    const int lane = tid & 31;
    const int m0 = blockIdx.y * 128, n0 = blockIdx.x * 256;
    if (blockIdx.z && n0 >= n_lim1) return;   // vy skip for y-QKV
    const int wm = (wid & 1) * 64;
    const int wn = (wid >> 1) * 64;
    const int S  = K / 16;

    const __half* A_h = blockIdx.z ? Ah1 : Ah0;
    const __half* A_l = blockIdx.z ? Al1 : Al0;
    float*        C   = blockIdx.z ? C1  : C0;

    const uint32_t sbase = smem_u32(sh);
    const int ld_row = tid >> 1;
    const int ld_c   = (tid & 1) << 3;

    auto issue_stage = [&](int s, int buf) {
        const int kb = s * 16;
        const uint32_t so = sbase + (uint32_t)buf * STGB;
        const uint32_t ro = (uint32_t)(ld_row * LDH2 + ld_c) * 2u;
        const uint32_t r2 = (uint32_t)((ld_row + 128) * LDH2 + ld_c) * 2u;
        const size_t ga  = (size_t)(m0 + ld_row) * K + kb + ld_c;
        const size_t gb  = (size_t)(n0 + ld_row) * K + kb + ld_c;
        const size_t gb2 = (size_t)(n0 + ld_row + 128) * K + kb + ld_c;
        cp_async16(so + ro,                        A_h + ga);
        cp_async16(so + (uint32_t)(ACH*2) + ro,    A_l + ga);
        cp_async16(so + (uint32_t)(2*ACH*2) + ro,  Bh + gb);
        cp_async16(so + (uint32_t)(2*ACH*2) + r2,  Bh + gb2);
    };

    float acc[4][8][4];
#pragma unroll
    for (int i = 0; i < 4; i++)
#pragma unroll
        for (int j = 0; j < 8; j++)
#pragma unroll
            for (int r = 0; r < 4; r++) acc[i][j][r] = 0.f;

    const int a_off = (wm + (lane & 15)) * LDH2 + ((lane >> 4) << 3);
    const int b_off = (wn + ((lane >> 4) << 3) + (lane & 7)) * LDH2 + (((lane >> 3) & 1) << 3);

    issue_stage(0, 0); cp_commit();
    issue_stage(1, 1); cp_commit();
    issue_stage(2, 2); cp_commit();

    for (int s = 0; s < S; s++) {
        if (s + 2 < S)      cp_wait2();
        else if (s + 1 < S) cp_wait1();
        else                cp_wait0();
        __syncthreads();
        if (s + 3 < S) { issue_stage(s + 3, (s + 3) & 3); cp_commit(); }

        const uint32_t stg = sbase + (uint32_t)((s & 3) * STGB);

        uint32_t ah[4][4], bh[8][2], t[4][4];
#pragma unroll
        for (int mt = 0; mt < 4; mt++)
            ldsm_x4(stg + (uint32_t)(a_off + mt * 16 * LDH2) * 2u,
                    ah[mt][0], ah[mt][1], ah[mt][2], ah[mt][3]);
#pragma unroll
        for (int p = 0; p < 4; p++)
            ldsm_x4(stg + (uint32_t)(2*ACH + b_off + p * 16 * LDH2) * 2u,
                    bh[p*2][0], bh[p*2][1], bh[p*2+1][0], bh[p*2+1][1]);

        // pass 1: Ah * Bh
#pragma unroll
        for (int mt = 0; mt < 4; mt++)
#pragma unroll
            for (int nt = 0; nt < 8; nt++)
                mma_f16(acc[mt][nt], ah[mt], bh[nt][0], bh[nt][1]);

        // pass 2: Al * Bh
#pragma unroll
        for (int mt = 0; mt < 4; mt++)
            ldsm_x4(stg + (uint32_t)(ACH + a_off + mt * 16 * LDH2) * 2u,
                    t[mt][0], t[mt][1], t[mt][2], t[mt][3]);
#pragma unroll
        for (int mt = 0; mt < 4; mt++)
#pragma unroll
            for (int nt = 0; nt < 8; nt++)
                mma_f16(acc[mt][nt], t[mt], bh[nt][0], bh[nt][1]);
    }

    // ---- epilogue: fp32 (+bias) ----
#pragma unroll
    for (int mt = 0; mt < 4; mt++) {
        int row0 = m0 + wm + mt * 16 + (lane >> 2);
#pragma unroll
        for (int nt = 0; nt < 8; nt++) {
            int col = n0 + wn + nt * 8 + (lane & 3) * 2;
            float b0 = 0.f, b1 = 0.f;
            if (bias) { b0 = __ldg(bias + col); b1 = __ldg(bias + col + 1); }
            float2 v0 = make_float2(acc[mt][nt][0] + b0, acc[mt][nt][1] + b1);
            float2 v1 = make_float2(acc[mt][nt][2] + b0, acc[mt][nt][3] + b1);
            *(float2*)(C + (size_t)row0 * N + col)       = v0;
            *(float2*)(C + (size_t)(row0 + 8) * N + col) = v1;
        }
    }
}

// ============================================================
// Dual-softmax flash attention, fp16 limbs.
// Q: hi+lo; K: hi; V: hi; P: hi.  S = (Qh+Ql)Kh; O = Ph Vh.
// Double-buffered K/V, register prefetch, 1 sync/iter.
// ============================================================
#define AQS 72
#define OQ1H 0
#define OQ1L (128*AQS)
#define OQ2H (2*128*AQS)
#define OQ2L (3*128*AQS)
#define OKV  (4*128*AQS)
#define KVH  (2*64*AQS)                   // Kh, Vh
#define ATT_SMEM ((OKV + 2*KVH) * 2)      // 110592 bytes

__global__ __launch_bounds__(256, 1) void attention_mma()
{
    extern __shared__ __align__(16) __half sh[];
    const uint32_t sb = smem_u32(sh);
    const int tid  = threadIdx.x;
    const int wid  = tid >> 5;
    const int lane = tid & 31;
    const int wm   = wid * 16;

    const int b    = blockIdx.z;
    const int h    = blockIdx.y >> 1;
    const int pair = blockIdx.y & 1;
    const int q0   = blockIdx.x * 128;

    const float* bx = g_qkv_x + (size_t)b * SEQ * QKV_DIM;
    const float* by = g_qkv_y + (size_t)b * SEQ * QKV_DIM;
    const int hoff  = h * HD;

    const float *Q1src, *Q2src, *Ksrc;
    float* outp;
    if (pair == 0) { Q1src = bx + C_DIM; Q2src = by;  Ksrc = bx + 2 * C_DIM; outp = g_att_x; }
    else           { Q1src = by + C_DIM; Q2src = bx;  Ksrc = by + 2 * C_DIM; outp = g_att_y; }
    const float* Vsrc = bx + 3 * C_DIM;   // vy = vx in the reference

    const int v_jp = tid & 31;
    const int v_d0 = (tid >> 5) * 8;

    // ---- load Q tiles as pre-scaled fp16 limbs ----
#pragma unroll
    for (int u = 0; u < 8; u++) {
        int idx = u * 256 + tid;
        int row = idx >> 4;
        int c4  = (idx & 15) << 2;
        float4 v1 = *(const float4*)(Q1src + (size_t)(q0 + row) * QKV_DIM + hoff + c4);
        float4 v2 = *(const float4*)(Q2src + (size_t)(q0 + row) * QKV_DIM + hoff + c4);
        v1.x *= 0.125f; v1.y *= 0.125f; v1.z *= 0.125f; v1.w *= 0.125f;
        v2.x *= -0.125f; v2.y *= -0.125f; v2.z *= -0.125f; v2.w *= -0.125f;
        uint2 hi, lo;
        int off = row * AQS + c4;
        split4h(v1, hi, lo);
        *(uint2*)(sh + OQ1H + off) = hi;
        *(uint2*)(sh + OQ1L + off) = lo;
        split4h(v2, hi, lo);
        *(uint2*)(sh + OQ2H + off) = hi;
        *(uint2*)(sh + OQ2L + off) = lo;
    }

    // ---- load KV tile 0 (K: [j][d] hi; V: [d][j] hi, transposed store) ----
    {
#pragma unroll
        for (int u = 0; u < 4; u++) {
            int idx = u * 256 + tid;
            int row = idx >> 4;
            int c4  = (idx & 15) << 2;
            float4 kv = *(const float4*)(Ksrc + (size_t)row * QKV_DIM + hoff + c4);
            *(uint2*)(sh + OKV + row * AQS + c4) = hi4h(kv);
        }
        const float* v0p = Vsrc + (size_t)(2 * v_jp)     * QKV_DIM + hoff + v_d0;
        const float* v1p = Vsrc + (size_t)(2 * v_jp + 1) * QKV_DIM + hoff + v_d0;
        float4 va0 = *(const float4*)(v0p);
        float4 va1 = *(const float4*)(v0p + 4);
        float4 vb0 = *(const float4*)(v1p);
        float4 vb1 = *(const float4*)(v1p + 4);
        float f0[8] = {va0.x, va0.y, va0.z, va0.w, va1.x, va1.y, va1.z, va1.w};
        float f1[8] = {vb0.x, vb0.y, vb0.z, vb0.w, vb1.x, vb1.y, vb1.z, vb1.w};
#pragma unroll
        for (int i = 0; i < 8; i++)
            *(uint32_t*)(sh + OKV + 64*AQS + (v_d0 + i) * AQS + 2 * v_jp) =
                pack_h2(__float2half_rn(f0[i]), __float2half_rn(f1[i]));
    }
    __syncthreads();

    float o1[8][4], o2[8][4];
#pragma unroll
    for (int d = 0; d < 8; d++)
#pragma unroll
        for (int r = 0; r < 4; r++) { o1[d][r] = 0.f; o2[d][r] = 0.f; }
    float m1lo = -1e30f, m1hi = -1e30f, l1lo = 0.f, l1hi = 0.f;
    float m2lo = -1e30f, m2hi = -1e30f, l2lo = 0.f, l2hi = 0.f;

    const uint32_t a_base = (uint32_t)((wm + (lane & 15)) * AQS + ((lane >> 4) << 3)) * 2u;
    const uint32_t b_base = (uint32_t)((((lane >> 4) << 3) + (lane & 7)) * AQS
                                       + (((lane >> 3) & 1) << 3)) * 2u;

    for (int kt = 0; kt < 16; kt++) {
        const int cur = kt & 1;
        const uint32_t kvb = (uint32_t)(OKV + cur * KVH) * 2u;

        // ---- prefetch next KV tile into registers ----
        float4 kpre[4], vpre[4];
        if (kt < 15) {
            const int j0n = (kt + 1) * 64;
#pragma unroll
            for (int u = 0; u < 4; u++) {
                int idx = u * 256 + tid;
                int row = idx >> 4;
                int c4  = (idx & 15) << 2;
                kpre[u] = *(const float4*)(Ksrc + (size_t)(j0n + row) * QKV_DIM + hoff + c4);
            }
            const float* v0p = Vsrc + (size_t)(j0n + 2 * v_jp)     * QKV_DIM + hoff + v_d0;
            const float* v1p = Vsrc + (size_t)(j0n + 2 * v_jp + 1) * QKV_DIM + hoff + v_d0;
            vpre[0] = *(const float4*)(v0p);
            vpre[1] = *(const float4*)(v0p + 4);
            vpre[2] = *(const float4*)(v1p);
            vpre[3] = *(const float4*)(v1p + 4);
        }

        // ---- S = Q K^T (2-pass: Qh*Kh + Ql*Kh), stream-interleaved ----
        float s1[8][4], s2[8][4];
#pragma unroll
        for (int n = 0; n < 8; n++)
#pragma unroll
            for (int r = 0; r < 4; r++) { s1[n][r] = 0.f; s2[n][r] = 0.f; }

#pragma unroll
        for (int ks = 0; ks < 4; ks++) {
            const uint32_t kofs = (uint32_t)(ks * 16) * 2u;
            uint32_t a1h[4], a1l[4], a2h[4], a2l[4];
            ldsm_x4(sb + OQ1H*2u + a_base + kofs, a1h[0], a1h[1], a1h[2], a1h[3]);
            ldsm_x4(sb + OQ1L*2u + a_base + kofs, a1l[0], a1l[1], a1l[2], a1l[3]);
            ldsm_x4(sb + OQ2H*2u + a_base + kofs, a2h[0], a2h[1], a2h[2], a2h[3]);
            ldsm_x4(sb + OQ2L*2u + a_base + kofs, a2l[0], a2l[1], a2l[2], a2l[3]);
#pragma unroll
            for (int jt = 0; jt < 4; jt++) {
                uint32_t rb = sb + kvb + b_base + (uint32_t)(jt * 16 * AQS) * 2u + kofs;
                uint32_t bh[2][2];
                ldsm_x4(rb, bh[0][0], bh[0][1], bh[1][0], bh[1][1]);
#pragma unroll
                for (int q = 0; q < 2; q++) {
                    int nt = jt * 2 + q;
                    mma_f16(s1[nt], a1h, bh[q][0], bh[q][1]);
                    mma_f16(s2[nt], a2h, bh[q][0], bh[q][1]);
                    mma_f16(s1[nt], a1l, bh[q][0], bh[q][1]);
                    mma_f16(s2[nt], a2l, bh[q][0], bh[q][1]);
                }
            }
        }

        // ---- store prefetched tile into the other buffer ----
        if (kt < 15) {
            const int nb = OKV + (cur ^ 1) * KVH;
#pragma unroll
            for (int u = 0; u < 4; u++) {
                int idx = u * 256 + tid;
                int row = idx >> 4;
                int c4  = (idx & 15) << 2;
                *(uint2*)(sh + nb + row * AQS + c4) = hi4h(kpre[u]);
            }
            float f0[8] = {vpre[0].x, vpre[0].y, vpre[0].z, vpre[0].w,
                           vpre[1].x, vpre[1].y, vpre[1].z, vpre[1].w};
            float f1[8] = {vpre[2].x, vpre[2].y, vpre[2].z, vpre[2].w,
                           vpre[3].x, vpre[3].y, vpre[3].z, vpre[3].w};
#pragma unroll
            for (int i = 0; i < 8; i++)
                *(uint32_t*)(sh + nb + 64*AQS + (v_d0 + i) * AQS + 2 * v_jp) =
                    pack_h2(__float2half_rn(f0[i]), __float2half_rn(f1[i]));
        }

        // ---- online softmax (per stream), P as fp16 hi ----
        uint32_t p1h[8][2], p2h[8][2];
        {
            float mxlo = -1e30f, mxhi = -1e30f;
#pragma unroll
            for (int n = 0; n < 8; n++) {
                mxlo = fmaxf(mxlo, fmaxf(s1[n][0], s1[n][1]));
                mxhi = fmaxf(mxhi, fmaxf(s1[n][2], s1[n][3]));
            }
            mxlo = fmaxf(mxlo, __shfl_xor_sync(0xffffffffu, mxlo, 1));
            mxlo = fmaxf(mxlo, __shfl_xor_sync(0xffffffffu, mxlo, 2));
            mxhi = fmaxf(mxhi, __shfl_xor_sync(0xffffffffu, mxhi, 1));
            mxhi = fmaxf(mxhi, __shfl_xor_sync(0xffffffffu, mxhi, 2));
            float mnlo = fmaxf(m1lo, mxlo), mnhi = fmaxf(m1hi, mxhi);
            float clo = __expf(m1lo - mnlo), chi = __expf(m1hi - mnhi);
            m1lo = mnlo; m1hi = mnhi;
            float sl = 0.f, shh = 0.f;
#pragma unroll
            for (int n = 0; n < 8; n++) {
                float p0 = __expf(s1[n][0] - mnlo);
                float p1 = __expf(s1[n][1] - mnlo);
                float p2 = __expf(s1[n][2] - mnhi);
                float p3 = __expf(s1[n][3] - mnhi);
                sl += p0 + p1; shh += p2 + p3;
                p1h[n][0] = pack_h2(__float2half_rn(p0), __float2half_rn(p1));
                p1h[n][1] = pack_h2(__float2half_rn(p2), __float2half_rn(p3));
            }
            sl  += __shfl_xor_sync(0xffffffffu, sl, 1);
            sl  += __shfl_xor_sync(0xffffffffu, sl, 2);
            shh += __shfl_xor_sync(0xffffffffu, shh, 1);
            shh += __shfl_xor_sync(0xffffffffu, shh, 2);
            l1lo = l1lo * clo + sl; l1hi = l1hi * chi + shh;
#pragma unroll
            for (int d = 0; d < 8; d++) {
                o1[d][0] *= clo; o1[d][1] *= clo;
                o1[d][2] *= chi; o1[d][3] *= chi;
            }
        }
        {
            float mxlo = -1e30f, mxhi = -1e30f;
#pragma unroll
            for (int n = 0; n < 8; n++) {
                mxlo = fmaxf(mxlo, fmaxf(s2[n][0], s2[n][1]));
                mxhi = fmaxf(mxhi, fmaxf(s2[n][2], s2[n][3]));
            }
            mxlo = fmaxf(mxlo, __shfl_xor_sync(0xffffffffu, mxlo, 1));
            mxlo = fmaxf(mxlo, __shfl_xor_sync(0xffffffffu, mxlo, 2));
            mxhi = fmaxf(mxhi, __shfl_xor_sync(0xffffffffu, mxhi, 1));
            mxhi = fmaxf(mxhi, __shfl_xor_sync(0xffffffffu, mxhi, 2));
            float mnlo = fmaxf(m2lo, mxlo), mnhi = fmaxf(m2hi, mxhi);
            float clo = __expf(m2lo - mnlo), chi = __expf(m2hi - mnhi);
            m2lo = mnlo; m2hi = mnhi;
            float sl = 0.f, shh = 0.f;
#pragma unroll
            for (int n = 0; n < 8; n++) {
                float p0 = __expf(s2[n][0] - mnlo);
                float p1 = __expf(s2[n][1] - mnlo);
                float p2 = __expf(s2[n][2] - mnhi);
                float p3 = __expf(s2[n][3] - mnhi);
                sl += p0 + p1; shh += p2 + p3;
                p2h[n][0] = pack_h2(__float2half_rn(p0), __float2half_rn(p1));
                p2h[n][1] = pack_h2(__float2half_rn(p2), __float2half_rn(p3));
            }
            sl  += __shfl_xor_sync(0xffffffffu, sl, 1);
            sl  += __shfl_xor_sync(0xffffffffu, sl, 2);
            shh += __shfl_xor_sync(0xffffffffu, shh, 1);
            shh += __shfl_xor_sync(0xffffffffu, shh, 2);
            l2lo = l2lo * clo + sl; l2hi = l2hi * chi + shh;
#pragma unroll
            for (int d = 0; d < 8; d++) {
                o2[d][0] *= clo; o2[d][1] *= clo;
                o2[d][2] *= chi; o2[d][3] *= chi;
            }
        }

        // ---- O += P V (1-pass: Ph*Vh) ----
#pragma unroll
        for (int ks = 0; ks < 4; ks++) {
            uint32_t a1f[4] = { p1h[2*ks][0], p1h[2*ks][1], p1h[2*ks+1][0], p1h[2*ks+1][1] };
            uint32_t a2f[4] = { p2h[2*ks][0], p2h[2*ks][1], p2h[2*ks+1][0], p2h[2*ks+1][1] };
            const uint32_t kofs = (uint32_t)(ks * 16) * 2u;
#pragma unroll
            for (int dt2 = 0; dt2 < 4; dt2++) {
                uint32_t rb = sb + kvb + (uint32_t)(64*AQS)*2u + b_base
                            + (uint32_t)(dt2 * 16 * AQS) * 2u + kofs;
                uint32_t vh[2][2];
                ldsm_x4(rb, vh[0][0], vh[0][1], vh[1][0], vh[1][1]);
#pragma unroll
                for (int q = 0; q < 2; q++) {
                    int dt = dt2 * 2 + q;
                    mma_f16(o1[dt], a1f, vh[q][0], vh[q][1]);
                    mma_f16(o2[dt], a2f, vh[q][0], vh[q][1]);
                }
            }
        }

        if (kt < 15) __syncthreads();
    }

    // ---- epilogue: out = O1/l1 + O2/l2 (fp32) ----
    const float i1lo = 1.f / l1lo, i1hi = 1.f / l1hi;
    const float i2lo = 1.f / l2lo, i2hi = 1.f / l2hi;
    float* obase = outp + (size_t)b * SEQ * C_DIM;
    const int r0 = q0 + wm + (lane >> 2);
    const int cb = hoff + (lane & 3) * 2;
#pragma unroll
    for (int dt = 0; dt < 8; dt++) {
        int col = cb + dt * 8;
        float2 vlo = make_float2(o1[dt][0] * i1lo + o2[dt][0] * i2lo,
                                 o1[dt][1] * i1lo + o2[dt][1] * i2lo);
        float2 vhi = make_float2(o1[dt][2] * i1hi + o2[dt][2] * i2hi,
                                 o1[dt][3] * i1hi + o2[dt][3] * i2hi);
        *(float2*)(obase + (size_t)r0 * C_DIM + col)       = vlo;
        *(float2*)(obase + (size_t)(r0 + 8) * C_DIM + col) = vhi;
    }
}

// ============================================================
extern "C" void kernel_launch(void* const* d_in, const int* in_sizes, int n_in,
                              void* d_out, int out_size)
{
    const float* x      = (const float*)d_in[0];
    const float* y      = (const float*)d_in[1];
    const float* w_qkv  = (const float*)d_in[2];
    const float* w_proj = (const float*)d_in[3];
    const float* b_proj = (const float*)d_in[4];
    float* out = (float*)d_out;

    float *qx, *qy, *ax, *ay;
    __half *xh, *xl, *yh, *yl, *wqh, *wql, *wph, *wpl;
    __half *axh, *axl, *ayh, *ayl;
    cudaGetSymbolAddress((void**)&qx,  g_qkv_x);
    cudaGetSymbolAddress((void**)&qy,  g_qkv_y);
    cudaGetSymbolAddress((void**)&ax,  g_att_x);
    cudaGetSymbolAddress((void**)&ay,  g_att_y);
    cudaGetSymbolAddress((void**)&xh,  g_x_hi);     cudaGetSymbolAddress((void**)&xl,  g_x_lo);
    cudaGetSymbolAddress((void**)&yh,  g_y_hi);     cudaGetSymbolAddress((void**)&yl,  g_y_lo);
    cudaGetSymbolAddress((void**)&wqh, g_wqkv_hi);  cudaGetSymbolAddress((void**)&wql, g_wqkv_lo);
    cudaGetSymbolAddress((void**)&wph, g_wproj_hi); cudaGetSymbolAddress((void**)&wpl, g_wproj_lo);
    cudaGetSymbolAddress((void**)&axh, g_ax_hi);    cudaGetSymbolAddress((void**)&axl, g_ax_lo);
    cudaGetSymbolAddress((void**)&ayh, g_ay_hi);    cudaGetSymbolAddress((void**)&ayl, g_ay_lo);

    cudaFuncSetAttribute(gemm_mma,
                         cudaFuncAttributeMaxDynamicSharedMemorySize, GEMM_SMEM);
    cudaFuncSetAttribute(attention_mma,
                         cudaFuncAttributeMaxDynamicSharedMemorySize, ATT_SMEM);

    // 0) fp32 -> fp16 limb pre-splits
    split_kernel<<<(M_ROWS*C_DIM/4 + 255)/256, 256>>>(x, xh, xl, M_ROWS*C_DIM/4);
    split_kernel<<<(M_ROWS*C_DIM/4 + 255)/256, 256>>>(y, yh, yl, M_ROWS*C_DIM/4);
    split_kernel<<<(QKV_DIM*C_DIM/4 + 255)/256, 256>>>(w_qkv, wqh, wql, QKV_DIM*C_DIM/4);
    split_kernel<<<(C_DIM*C_DIM/4 + 255)/256, 256>>>(w_proj, wph, wpl, C_DIM*C_DIM/4);

    // 1) QKV projections, 2-pass fp16; y-branch skips unused vy (N<2304)
    dim3 g1(QKV_DIM / 256, M_ROWS / 128, 2);
    gemm_mma<<<g1, 256, GEMM_SMEM>>>(xh, xl, yh, yl, wqh, nullptr,
                                     qx, qy, M_ROWS, QKV_DIM, C_DIM, 2304);

    // 2) fused dual-softmax attention (fp16, PV 1-pass)
    attention_mma<<<dim3(SEQ / 128, HEADS * 2, BATCH), 256, ATT_SMEM>>>();

    // 2b) split attention outputs to fp16 limbs for proj
    split_kernel<<<(M_ROWS*C_DIM/4 + 255)/256, 256>>>(ax, axh, axl, M_ROWS*C_DIM/4);
    split_kernel<<<(M_ROWS*C_DIM/4 + 255)/256, 256>>>(ay, ayh, ayl, M_ROWS*C_DIM/4);

    // 3) output projections + bias, 2-pass fp16
    dim3 g2(C_DIM / 256, M_ROWS / 128, 2);
    gemm_mma<<<g2, 256, GEMM_SMEM>>>(axh, axl, ayh, ayl, wph, b_proj,
                                     out, out + (size_t)M_ROWS * C_DIM,
                                     M_ROWS, C_DIM, C_DIM, C_DIM);
}

// round 10
// speedup vs baseline: 1.5081x; 1.5081x over previous
#include <cuda_runtime.h>
#include <cuda_fp16.h>
#include <cstdint>

#define C_DIM   768
#define QKV_DIM 3072
#define BATCH   4
#define SEQ     1024
#define HEADS   12
#define HD      64
#define M_ROWS  (BATCH*SEQ)   // 4096

// -------- scratch (allocation-free: device globals) --------
__device__ float g_qkv_x[M_ROWS*QKV_DIM];
__device__ float g_qkv_y[M_ROWS*QKV_DIM];
__device__ float g_att_x[M_ROWS*C_DIM];
__device__ float g_att_y[M_ROWS*C_DIM];
__device__ __half g_x_hi[M_ROWS*C_DIM],     g_x_lo[M_ROWS*C_DIM];
__device__ __half g_y_hi[M_ROWS*C_DIM],     g_y_lo[M_ROWS*C_DIM];
__device__ __half g_wqkv_hi[QKV_DIM*C_DIM], g_wqkv_lo[QKV_DIM*C_DIM];
__device__ __half g_wproj_hi[C_DIM*C_DIM],  g_wproj_lo[C_DIM*C_DIM];
__device__ __half g_ax_hi[M_ROWS*C_DIM],    g_ax_lo[M_ROWS*C_DIM];
__device__ __half g_ay_hi[M_ROWS*C_DIM],    g_ay_lo[M_ROWS*C_DIM];

// ============================================================
// helpers
// ============================================================
__device__ __forceinline__ uint32_t smem_u32(const void* p) {
    uint32_t a;
    asm("{ .reg .u64 t; cvta.to.shared.u64 t, %1; cvt.u32.u64 %0, t; }"
        : "=r"(a) : "l"(p));
    return a;
}

__device__ __forceinline__ void ldsm_x4(uint32_t addr, uint32_t& r0, uint32_t& r1,
                                        uint32_t& r2, uint32_t& r3) {
    asm volatile("ldmatrix.sync.aligned.m8n8.x4.shared.b16 {%0,%1,%2,%3}, [%4];"
                 : "=r"(r0), "=r"(r1), "=r"(r2), "=r"(r3) : "r"(addr));
}

__device__ __forceinline__ void mma_f16(float* c, const uint32_t* a,
                                        uint32_t b0, uint32_t b1) {
    asm volatile(
        "mma.sync.aligned.m16n8k16.row.col.f32.f16.f16.f32 "
        "{%0,%1,%2,%3}, {%4,%5,%6,%7}, {%8,%9}, {%0,%1,%2,%3};"
        : "+f"(c[0]), "+f"(c[1]), "+f"(c[2]), "+f"(c[3])
        : "r"(a[0]), "r"(a[1]), "r"(a[2]), "r"(a[3]), "r"(b0), "r"(b1));
}

__device__ __forceinline__ void cp_async16(uint32_t saddr, const void* gptr) {
    asm volatile("cp.async.cg.shared.global [%0], [%1], 16;"
                 :: "r"(saddr), "l"(gptr));
}
__device__ __forceinline__ void cp_commit() {
    asm volatile("cp.async.commit_group;" ::: "memory");
}
__device__ __forceinline__ void cp_wait0() { asm volatile("cp.async.wait_group 0;" ::: "memory"); }
__device__ __forceinline__ void cp_wait1() { asm volatile("cp.async.wait_group 1;" ::: "memory"); }
__device__ __forceinline__ void cp_wait2() { asm volatile("cp.async.wait_group 2;" ::: "memory"); }

__device__ __forceinline__ uint32_t pack_h2(__half a, __half b) {
    return ((uint32_t)__half_as_ushort(b) << 16) | (uint32_t)__half_as_ushort(a);
}

// split fp32 float4 -> hi/lo fp16 limb pairs
__device__ __forceinline__ void split4h(float4 v, uint2& hi, uint2& lo) {
    __half h0 = __float2half_rn(v.x);
    __half h1 = __float2half_rn(v.y);
    __half h2 = __float2half_rn(v.z);
    __half h3 = __float2half_rn(v.w);
    __half l0 = __float2half_rn(v.x - __half2float(h0));
    __half l1 = __float2half_rn(v.y - __half2float(h1));
    __half l2 = __float2half_rn(v.z - __half2float(h2));
    __half l3 = __float2half_rn(v.w - __half2float(h3));
    hi.x = pack_h2(h0, h1); hi.y = pack_h2(h2, h3);
    lo.x = pack_h2(l0, l1); lo.y = pack_h2(l2, l3);
}

// fp32 float4 -> fp16 hi only
__device__ __forceinline__ uint2 hi4h(float4 v) {
    return make_uint2(pack_h2(__float2half_rn(v.x), __float2half_rn(v.y)),
                      pack_h2(__float2half_rn(v.z), __float2half_rn(v.w)));
}

// ============================================================
// fp32 -> fp16 limb split kernel (memory-bound pre-pass)
// ============================================================
__global__ __launch_bounds__(256) void split_kernel(
    const float* __restrict__ src, __half* __restrict__ hi,
    __half* __restrict__ lo, int n4)
{
    int i = blockIdx.x * 256 + threadIdx.x;
    if (i < n4) {
        float4 v = ((const float4*)src)[i];
        uint2 h, l;
        split4h(v, h, l);
        ((uint2*)hi)[i] = h;
        ((uint2*)lo)[i] = l;
    }
}

// ============================================================
// split-fp16 mma.sync GEMM, limb inputs. 2-pass: AhBh + AlBh.
// CTA tile 128m x 256n, 8 warps (2m x 4n), warp tile 64x64.
// BK=16, 4-deep cp.async ring, 1 sync/stage.
// ============================================================
#define LDH2 24                        // halves per row (16 + 8 pad)
#define ACH  (128 * LDH2)              // 3072 halves per A limb array
#define BCH  (256 * LDH2)              // 6144 halves per B array
#define STGH2 (2*ACH + BCH)            // 12288 halves per stage
#define STGB  (STGH2 * 2)              // 24576 bytes per stage
#define GEMM_SMEM (4 * STGB)           // 98304

__global__ __launch_bounds__(256, 1) void gemm_mma(
    const __half* __restrict__ Ah0, const __half* __restrict__ Al0,
    const __half* __restrict__ Ah1, const __half* __restrict__ Al1,
    const __half* __restrict__ Bh,
    const float* __restrict__ bias,
    float* __restrict__ C0, float* __restrict__ C1,
    int M, int N, int K, int n_lim1)
{
    extern __shared__ __align__(16) __half sh[];
    const int tid  = threadIdx.x;
    const int wid  = tid >> 5;
    const int lane = tid & 31;
    const int m0 = blockIdx.y * 128, n0 = blockIdx.x * 256;
    if (blockIdx.z && n0 >= n_lim1) return;   // vy skip for y-QKV
    const int wm = (wid & 1) * 64;
    const int wn = (wid >> 1) * 64;
    const int S  = K / 16;

    const __half* A_h = blockIdx.z ? Ah1 : Ah0;
    const __half* A_l = blockIdx.z ? Al1 : Al0;
    float*        C   = blockIdx.z ? C1  : C0;

    const uint32_t sbase = smem_u32(sh);
    const int ld_row = tid >> 1;
    const int ld_c   = (tid & 1) << 3;

    auto issue_stage = [&](int s, int buf) {
        const int kb = s * 16;
        const uint32_t so = sbase + (uint32_t)buf * STGB;
        const uint32_t ro = (uint32_t)(ld_row * LDH2 + ld_c) * 2u;
        const uint32_t r2 = (uint32_t)((ld_row + 128) * LDH2 + ld_c) * 2u;
        const size_t ga  = (size_t)(m0 + ld_row) * K + kb + ld_c;
        const size_t gb  = (size_t)(n0 + ld_row) * K + kb + ld_c;
        const size_t gb2 = (size_t)(n0 + ld_row + 128) * K + kb + ld_c;
        cp_async16(so + ro,                        A_h + ga);
        cp_async16(so + (uint32_t)(ACH*2) + ro,    A_l + ga);
        cp_async16(so + (uint32_t)(2*ACH*2) + ro,  Bh + gb);
        cp_async16(so + (uint32_t)(2*ACH*2) + r2,  Bh + gb2);
    };

    float acc[4][8][4];
#pragma unroll
    for (int i = 0; i < 4; i++)
#pragma unroll
        for (int j = 0; j < 8; j++)
#pragma unroll
            for (int r = 0; r < 4; r++) acc[i][j][r] = 0.f;

    const int a_off = (wm + (lane & 15)) * LDH2 + ((lane >> 4) << 3);
    const int b_off = (wn + ((lane >> 4) << 3) + (lane & 7)) * LDH2 + (((lane >> 3) & 1) << 3);

    issue_stage(0, 0); cp_commit();
    issue_stage(1, 1); cp_commit();
    issue_stage(2, 2); cp_commit();

    for (int s = 0; s < S; s++) {
        if (s + 2 < S)      cp_wait2();
        else if (s + 1 < S) cp_wait1();
        else                cp_wait0();
        __syncthreads();
        if (s + 3 < S) { issue_stage(s + 3, (s + 3) & 3); cp_commit(); }

        const uint32_t stg = sbase + (uint32_t)((s & 3) * STGB);

        uint32_t ah[4][4], bh[8][2], t[4][4];
#pragma unroll
        for (int mt = 0; mt < 4; mt++)
            ldsm_x4(stg + (uint32_t)(a_off + mt * 16 * LDH2) * 2u,
                    ah[mt][0], ah[mt][1], ah[mt][2], ah[mt][3]);
#pragma unroll
        for (int p = 0; p < 4; p++)
            ldsm_x4(stg + (uint32_t)(2*ACH + b_off + p * 16 * LDH2) * 2u,
                    bh[p*2][0], bh[p*2][1], bh[p*2+1][0], bh[p*2+1][1]);

        // pass 1: Ah * Bh
#pragma unroll
        for (int mt = 0; mt < 4; mt++)
#pragma unroll
            for (int nt = 0; nt < 8; nt++)
                mma_f16(acc[mt][nt], ah[mt], bh[nt][0], bh[nt][1]);

        // pass 2: Al * Bh
#pragma unroll
        for (int mt = 0; mt < 4; mt++)
            ldsm_x4(stg + (uint32_t)(ACH + a_off + mt * 16 * LDH2) * 2u,
                    t[mt][0], t[mt][1], t[mt][2], t[mt][3]);
#pragma unroll
        for (int mt = 0; mt < 4; mt++)
#pragma unroll
            for (int nt = 0; nt < 8; nt++)
                mma_f16(acc[mt][nt], t[mt], bh[nt][0], bh[nt][1]);
    }

    // ---- epilogue: fp32 (+bias) ----
#pragma unroll
    for (int mt = 0; mt < 4; mt++) {
        int row0 = m0 + wm + mt * 16 + (lane >> 2);
#pragma unroll
        for (int nt = 0; nt < 8; nt++) {
            int col = n0 + wn + nt * 8 + (lane & 3) * 2;
            float b0 = 0.f, b1 = 0.f;
            if (bias) { b0 = __ldg(bias + col); b1 = __ldg(bias + col + 1); }
            float2 v0 = make_float2(acc[mt][nt][0] + b0, acc[mt][nt][1] + b1);
            float2 v1 = make_float2(acc[mt][nt][2] + b0, acc[mt][nt][3] + b1);
            *(float2*)(C + (size_t)row0 * N + col)       = v0;
            *(float2*)(C + (size_t)(row0 + 8) * N + col) = v1;
        }
    }
}

// ============================================================
// Dual-softmax flash attention, fp16 limbs.
// Q: hi+lo; K: hi; V: hi; P: hi.  S = (Qh+Ql)Kh; O = Ph Vh.
// Double-buffered K/V, register prefetch, 1 sync/iter.
// ATT_SMEM padded above 116736 B to force 1 CTA/SM (2-CTA
// co-residency measured as a 290us regression in R9).
// ============================================================
#define AQS 72
#define OQ1H 0
#define OQ1L (128*AQS)
#define OQ2H (2*128*AQS)
#define OQ2L (3*128*AQS)
#define OKV  (4*128*AQS)
#define KVH  (2*64*AQS)                     // Kh, Vh
#define ATT_SMEM_DATA ((OKV + 2*KVH) * 2)   // 110592 bytes
#define ATT_SMEM 117760                     // padded: > 233472/2 -> 1 CTA/SM

__global__ __launch_bounds__(256, 1) void attention_mma()
{
    extern __shared__ __align__(16) __half sh[];
    const uint32_t sb = smem_u32(sh);
    const int tid  = threadIdx.x;
    const int wid  = tid >> 5;
    const int lane = tid & 31;
    const int wm   = wid * 16;

    const int b    = blockIdx.z;
    const int h    = blockIdx.y >> 1;
    const int pair = blockIdx.y & 1;
    const int q0   = blockIdx.x * 128;

    const float* bx = g_qkv_x + (size_t)b * SEQ * QKV_DIM;
    const float* by = g_qkv_y + (size_t)b * SEQ * QKV_DIM;
    const int hoff  = h * HD;

    const float *Q1src, *Q2src, *Ksrc;
    float* outp;
    if (pair == 0) { Q1src = bx + C_DIM; Q2src = by;  Ksrc = bx + 2 * C_DIM; outp = g_att_x; }
    else           { Q1src = by + C_DIM; Q2src = bx;  Ksrc = by + 2 * C_DIM; outp = g_att_y; }
    const float* Vsrc = bx + 3 * C_DIM;   // vy = vx in the reference

    const int v_jp = tid & 31;
    const int v_d0 = (tid >> 5) * 8;

    // ---- load Q tiles as pre-scaled fp16 limbs ----
#pragma unroll
    for (int u = 0; u < 8; u++) {
        int idx = u * 256 + tid;
        int row = idx >> 4;
        int c4  = (idx & 15) << 2;
        float4 v1 = *(const float4*)(Q1src + (size_t)(q0 + row) * QKV_DIM + hoff + c4);
        float4 v2 = *(const float4*)(Q2src + (size_t)(q0 + row) * QKV_DIM + hoff + c4);
        v1.x *= 0.125f; v1.y *= 0.125f; v1.z *= 0.125f; v1.w *= 0.125f;
        v2.x *= -0.125f; v2.y *= -0.125f; v2.z *= -0.125f; v2.w *= -0.125f;
        uint2 hi, lo;
        int off = row * AQS + c4;
        split4h(v1, hi, lo);
        *(uint2*)(sh + OQ1H + off) = hi;
        *(uint2*)(sh + OQ1L + off) = lo;
        split4h(v2, hi, lo);
        *(uint2*)(sh + OQ2H + off) = hi;
        *(uint2*)(sh + OQ2L + off) = lo;
    }

    // ---- load KV tile 0 (K: [j][d] hi; V: [d][j] hi, transposed store) ----
    {
#pragma unroll
        for (int u = 0; u < 4; u++) {
            int idx = u * 256 + tid;
            int row = idx >> 4;
            int c4  = (idx & 15) << 2;
            float4 kv = *(const float4*)(Ksrc + (size_t)row * QKV_DIM + hoff + c4);
            *(uint2*)(sh + OKV + row * AQS + c4) = hi4h(kv);
        }
        const float* v0p = Vsrc + (size_t)(2 * v_jp)     * QKV_DIM + hoff + v_d0;
        const float* v1p = Vsrc + (size_t)(2 * v_jp + 1) * QKV_DIM + hoff + v_d0;
        float4 va0 = *(const float4*)(v0p);
        float4 va1 = *(const float4*)(v0p + 4);
        float4 vb0 = *(const float4*)(v1p);
        float4 vb1 = *(const float4*)(v1p + 4);
        float f0[8] = {va0.x, va0.y, va0.z, va0.w, va1.x, va1.y, va1.z, va1.w};
        float f1[8] = {vb0.x, vb0.y, vb0.z, vb0.w, vb1.x, vb1.y, vb1.z, vb1.w};
#pragma unroll
        for (int i = 0; i < 8; i++)
            *(uint32_t*)(sh + OKV + 64*AQS + (v_d0 + i) * AQS + 2 * v_jp) =
                pack_h2(__float2half_rn(f0[i]), __float2half_rn(f1[i]));
    }
    __syncthreads();

    float o1[8][4], o2[8][4];
#pragma unroll
    for (int d = 0; d < 8; d++)
#pragma unroll
        for (int r = 0; r < 4; r++) { o1[d][r] = 0.f; o2[d][r] = 0.f; }
    float m1lo = -1e30f, m1hi = -1e30f, l1lo = 0.f, l1hi = 0.f;
    float m2lo = -1e30f, m2hi = -1e30f, l2lo = 0.f, l2hi = 0.f;

    const uint32_t a_base = (uint32_t)((wm + (lane & 15)) * AQS + ((lane >> 4) << 3)) * 2u;
    const uint32_t b_base = (uint32_t)((((lane >> 4) << 3) + (lane & 7)) * AQS
                                       + (((lane >> 3) & 1) << 3)) * 2u;

    for (int kt = 0; kt < 16; kt++) {
        const int cur = kt & 1;
        const uint32_t kvb = (uint32_t)(OKV + cur * KVH) * 2u;

        // ---- prefetch next KV tile into registers ----
        float4 kpre[4], vpre[4];
        if (kt < 15) {
            const int j0n = (kt + 1) * 64;
#pragma unroll
            for (int u = 0; u < 4; u++) {
                int idx = u * 256 + tid;
                int row = idx >> 4;
                int c4  = (idx & 15) << 2;
                kpre[u] = *(const float4*)(Ksrc + (size_t)(j0n + row) * QKV_DIM + hoff + c4);
            }
            const float* v0p = Vsrc + (size_t)(j0n + 2 * v_jp)     * QKV_DIM + hoff + v_d0;
            const float* v1p = Vsrc + (size_t)(j0n + 2 * v_jp + 1) * QKV_DIM + hoff + v_d0;
            vpre[0] = *(const float4*)(v0p);
            vpre[1] = *(const float4*)(v0p + 4);
            vpre[2] = *(const float4*)(v1p);
            vpre[3] = *(const float4*)(v1p + 4);
        }

        // ---- S = Q K^T (2-pass: Qh*Kh + Ql*Kh), stream-interleaved ----
        float s1[8][4], s2[8][4];
#pragma unroll
        for (int n = 0; n < 8; n++)
#pragma unroll
            for (int r = 0; r < 4; r++) { s1[n][r] = 0.f; s2[n][r] = 0.f; }

#pragma unroll
        for (int ks = 0; ks < 4; ks++) {
            const uint32_t kofs = (uint32_t)(ks * 16) * 2u;
            uint32_t a1h[4], a1l[4], a2h[4], a2l[4];
            ldsm_x4(sb + OQ1H*2u + a_base + kofs, a1h[0], a1h[1], a1h[2], a1h[3]);
            ldsm_x4(sb + OQ1L*2u + a_base + kofs, a1l[0], a1l[1], a1l[2], a1l[3]);
            ldsm_x4(sb + OQ2H*2u + a_base + kofs, a2h[0], a2h[1], a2h[2], a2h[3]);
            ldsm_x4(sb + OQ2L*2u + a_base + kofs, a2l[0], a2l[1], a2l[2], a2l[3]);
#pragma unroll
            for (int jt = 0; jt < 4; jt++) {
                uint32_t rb = sb + kvb + b_base + (uint32_t)(jt * 16 * AQS) * 2u + kofs;
                uint32_t bh[2][2];
                ldsm_x4(rb, bh[0][0], bh[0][1], bh[1][0], bh[1][1]);
#pragma unroll
                for (int q = 0; q < 2; q++) {
                    int nt = jt * 2 + q;
                    mma_f16(s1[nt], a1h, bh[q][0], bh[q][1]);
                    mma_f16(s2[nt], a2h, bh[q][0], bh[q][1]);
                    mma_f16(s1[nt], a1l, bh[q][0], bh[q][1]);
                    mma_f16(s2[nt], a2l, bh[q][0], bh[q][1]);
                }
            }
        }

        // ---- store prefetched tile into the other buffer ----
        if (kt < 15) {
            const int nb = OKV + (cur ^ 1) * KVH;
#pragma unroll
            for (int u = 0; u < 4; u++) {
                int idx = u * 256 + tid;
                int row = idx >> 4;
                int c4  = (idx & 15) << 2;
                *(uint2*)(sh + nb + row * AQS + c4) = hi4h(kpre[u]);
            }
            float f0[8] = {vpre[0].x, vpre[0].y, vpre[0].z, vpre[0].w,
                           vpre[1].x, vpre[1].y, vpre[1].z, vpre[1].w};
            float f1[8] = {vpre[2].x, vpre[2].y, vpre[2].z, vpre[2].w,
                           vpre[3].x, vpre[3].y, vpre[3].z, vpre[3].w};
#pragma unroll
            for (int i = 0; i < 8; i++)
                *(uint32_t*)(sh + nb + 64*AQS + (v_d0 + i) * AQS + 2 * v_jp) =
                    pack_h2(__float2half_rn(f0[i]), __float2half_rn(f1[i]));
        }

        // ---- online softmax (per stream), P as fp16 hi ----
        uint32_t p1h[8][2], p2h[8][2];
        {
            float mxlo = -1e30f, mxhi = -1e30f;
#pragma unroll
            for (int n = 0; n < 8; n++) {
                mxlo = fmaxf(mxlo, fmaxf(s1[n][0], s1[n][1]));
                mxhi = fmaxf(mxhi, fmaxf(s1[n][2], s1[n][3]));
            }
            mxlo = fmaxf(mxlo, __shfl_xor_sync(0xffffffffu, mxlo, 1));
            mxlo = fmaxf(mxlo, __shfl_xor_sync(0xffffffffu, mxlo, 2));
            mxhi = fmaxf(mxhi, __shfl_xor_sync(0xffffffffu, mxhi, 1));
            mxhi = fmaxf(mxhi, __shfl_xor_sync(0xffffffffu, mxhi, 2));
            float mnlo = fmaxf(m1lo, mxlo), mnhi = fmaxf(m1hi, mxhi);
            float clo = __expf(m1lo - mnlo), chi = __expf(m1hi - mnhi);
            m1lo = mnlo; m1hi = mnhi;
            float sl = 0.f, shh = 0.f;
#pragma unroll
            for (int n = 0; n < 8; n++) {
                float p0 = __expf(s1[n][0] - mnlo);
                float p1 = __expf(s1[n][1] - mnlo);
                float p2 = __expf(s1[n][2] - mnhi);
                float p3 = __expf(s1[n][3] - mnhi);
                sl += p0 + p1; shh += p2 + p3;
                p1h[n][0] = pack_h2(__float2half_rn(p0), __float2half_rn(p1));
                p1h[n][1] = pack_h2(__float2half_rn(p2), __float2half_rn(p3));
            }
            sl  += __shfl_xor_sync(0xffffffffu, sl, 1);
            sl  += __shfl_xor_sync(0xffffffffu, sl, 2);
            shh += __shfl_xor_sync(0xffffffffu, shh, 1);
            shh += __shfl_xor_sync(0xffffffffu, shh, 2);
            l1lo = l1lo * clo + sl; l1hi = l1hi * chi + shh;
#pragma unroll
            for (int d = 0; d < 8; d++) {
                o1[d][0] *= clo; o1[d][1] *= clo;
                o1[d][2] *= chi; o1[d][3] *= chi;
            }
        }
        {
            float mxlo = -1e30f, mxhi = -1e30f;
#pragma unroll
            for (int n = 0; n < 8; n++) {
                mxlo = fmaxf(mxlo, fmaxf(s2[n][0], s2[n][1]));
                mxhi = fmaxf(mxhi, fmaxf(s2[n][2], s2[n][3]));
            }
            mxlo = fmaxf(mxlo, __shfl_xor_sync(0xffffffffu, mxlo, 1));
            mxlo = fmaxf(mxlo, __shfl_xor_sync(0xffffffffu, mxlo, 2));
            mxhi = fmaxf(mxhi, __shfl_xor_sync(0xffffffffu, mxhi, 1));
            mxhi = fmaxf(mxhi, __shfl_xor_sync(0xffffffffu, mxhi, 2));
            float mnlo = fmaxf(m2lo, mxlo), mnhi = fmaxf(m2hi, mxhi);
            float clo = __expf(m2lo - mnlo), chi = __expf(m2hi - mnhi);
            m2lo = mnlo; m2hi = mnhi;
            float sl = 0.f, shh = 0.f;
#pragma unroll
            for (int n = 0; n < 8; n++) {
                float p0 = __expf(s2[n][0] - mnlo);
                float p1 = __expf(s2[n][1] - mnlo);
                float p2 = __expf(s2[n][2] - mnhi);
                float p3 = __expf(s2[n][3] - mnhi);
                sl += p0 + p1; shh += p2 + p3;
                p2h[n][0] = pack_h2(__float2half_rn(p0), __float2half_rn(p1));
                p2h[n][1] = pack_h2(__float2half_rn(p2), __float2half_rn(p3));
            }
            sl  += __shfl_xor_sync(0xffffffffu, sl, 1);
            sl  += __shfl_xor_sync(0xffffffffu, sl, 2);
            shh += __shfl_xor_sync(0xffffffffu, shh, 1);
            shh += __shfl_xor_sync(0xffffffffu, shh, 2);
            l2lo = l2lo * clo + sl; l2hi = l2hi * chi + shh;
#pragma unroll
            for (int d = 0; d < 8; d++) {
                o2[d][0] *= clo; o2[d][1] *= clo;
                o2[d][2] *= chi; o2[d][3] *= chi;
            }
        }

        // ---- O += P V (1-pass: Ph*Vh) ----
#pragma unroll
        for (int ks = 0; ks < 4; ks++) {
            uint32_t a1f[4] = { p1h[2*ks][0], p1h[2*ks][1], p1h[2*ks+1][0], p1h[2*ks+1][1] };
            uint32_t a2f[4] = { p2h[2*ks][0], p2h[2*ks][1], p2h[2*ks+1][0], p2h[2*ks+1][1] };
            const uint32_t kofs = (uint32_t)(ks * 16) * 2u;
#pragma unroll
            for (int dt2 = 0; dt2 < 4; dt2++) {
                uint32_t rb = sb + kvb + (uint32_t)(64*AQS)*2u + b_base
                            + (uint32_t)(dt2 * 16 * AQS) * 2u + kofs;
                uint32_t vh[2][2];
                ldsm_x4(rb, vh[0][0], vh[0][1], vh[1][0], vh[1][1]);
#pragma unroll
                for (int q = 0; q < 2; q++) {
                    int dt = dt2 * 2 + q;
                    mma_f16(o1[dt], a1f, vh[q][0], vh[q][1]);
                    mma_f16(o2[dt], a2f, vh[q][0], vh[q][1]);
                }
            }
        }

        if (kt < 15) __syncthreads();
    }

    // ---- epilogue: out = O1/l1 + O2/l2 (fp32) ----
    const float i1lo = 1.f / l1lo, i1hi = 1.f / l1hi;
    const float i2lo = 1.f / l2lo, i2hi = 1.f / l2hi;
    float* obase = outp + (size_t)b * SEQ * C_DIM;
    const int r0 = q0 + wm + (lane >> 2);
    const int cb = hoff + (lane & 3) * 2;
#pragma unroll
    for (int dt = 0; dt < 8; dt++) {
        int col = cb + dt * 8;
        float2 vlo = make_float2(o1[dt][0] * i1lo + o2[dt][0] * i2lo,
                                 o1[dt][1] * i1lo + o2[dt][1] * i2lo);
        float2 vhi = make_float2(o1[dt][2] * i1hi + o2[dt][2] * i2hi,
                                 o1[dt][3] * i1hi + o2[dt][3] * i2hi);
        *(float2*)(obase + (size_t)r0 * C_DIM + col)       = vlo;
        *(float2*)(obase + (size_t)(r0 + 8) * C_DIM + col) = vhi;
    }
}

// ============================================================
extern "C" void kernel_launch(void* const* d_in, const int* in_sizes, int n_in,
                              void* d_out, int out_size)
{
    const float* x      = (const float*)d_in[0];
    const float* y      = (const float*)d_in[1];
    const float* w_qkv  = (const float*)d_in[2];
    const float* w_proj = (const float*)d_in[3];
    const float* b_proj = (const float*)d_in[4];
    float* out = (float*)d_out;

    float *qx, *qy, *ax, *ay;
    __half *xh, *xl, *yh, *yl, *wqh, *wql, *wph, *wpl;
    __half *axh, *axl, *ayh, *ayl;
    cudaGetSymbolAddress((void**)&qx,  g_qkv_x);
    cudaGetSymbolAddress((void**)&qy,  g_qkv_y);
    cudaGetSymbolAddress((void**)&ax,  g_att_x);
    cudaGetSymbolAddress((void**)&ay,  g_att_y);
    cudaGetSymbolAddress((void**)&xh,  g_x_hi);     cudaGetSymbolAddress((void**)&xl,  g_x_lo);
    cudaGetSymbolAddress((void**)&yh,  g_y_hi);     cudaGetSymbolAddress((void**)&yl,  g_y_lo);
    cudaGetSymbolAddress((void**)&wqh, g_wqkv_hi);  cudaGetSymbolAddress((void**)&wql, g_wqkv_lo);
    cudaGetSymbolAddress((void**)&wph, g_wproj_hi); cudaGetSymbolAddress((void**)&wpl, g_wproj_lo);
    cudaGetSymbolAddress((void**)&axh, g_ax_hi);    cudaGetSymbolAddress((void**)&axl, g_ax_lo);
    cudaGetSymbolAddress((void**)&ayh, g_ay_hi);    cudaGetSymbolAddress((void**)&ayl, g_ay_lo);

    cudaFuncSetAttribute(gemm_mma,
                         cudaFuncAttributeMaxDynamicSharedMemorySize, GEMM_SMEM);
    cudaFuncSetAttribute(attention_mma,
                         cudaFuncAttributeMaxDynamicSharedMemorySize, ATT_SMEM);

    // 0) fp32 -> fp16 limb pre-splits
    split_kernel<<<(M_ROWS*C_DIM/4 + 255)/256, 256>>>(x, xh, xl, M_ROWS*C_DIM/4);
    split_kernel<<<(M_ROWS*C_DIM/4 + 255)/256, 256>>>(y, yh, yl, M_ROWS*C_DIM/4);
    split_kernel<<<(QKV_DIM*C_DIM/4 + 255)/256, 256>>>(w_qkv, wqh, wql, QKV_DIM*C_DIM/4);
    split_kernel<<<(C_DIM*C_DIM/4 + 255)/256, 256>>>(w_proj, wph, wpl, C_DIM*C_DIM/4);

    // 1) QKV projections, 2-pass fp16; y-branch skips unused vy (N<2304)
    dim3 g1(QKV_DIM / 256, M_ROWS / 128, 2);
    gemm_mma<<<g1, 256, GEMM_SMEM>>>(xh, xl, yh, yl, wqh, nullptr,
                                     qx, qy, M_ROWS, QKV_DIM, C_DIM, 2304);

    // 2) fused dual-softmax attention (fp16, PV 1-pass, smem-padded 1 CTA/SM)
    attention_mma<<<dim3(SEQ / 128, HEADS * 2, BATCH), 256, ATT_SMEM>>>();

    // 2b) split attention outputs to fp16 limbs for proj
    split_kernel<<<(M_ROWS*C_DIM/4 + 255)/256, 256>>>(ax, axh, axl, M_ROWS*C_DIM/4);
    split_kernel<<<(M_ROWS*C_DIM/4 + 255)/256, 256>>>(ay, ayh, ayl, M_ROWS*C_DIM/4);

    // 3) output projections + bias, 2-pass fp16
    dim3 g2(C_DIM / 256, M_ROWS / 128, 2);
    gemm_mma<<<g2, 256, GEMM_SMEM>>>(axh, axl, ayh, ayl, wph, b_proj,
                                     out, out + (size_t)M_ROWS * C_DIM,
                                     M_ROWS, C_DIM, C_DIM, C_DIM);
}

// round 11
// speedup vs baseline: 1.7165x; 1.1382x over previous
#include <cuda_runtime.h>
#include <cuda_fp16.h>
#include <cstdint>

#define C_DIM   768
#define QKV_DIM 3072
#define BATCH   4
#define SEQ     1024
#define HEADS   12
#define HD      64
#define M_ROWS  (BATCH*SEQ)   // 4096

// -------- scratch (allocation-free: device globals) --------
__device__ float g_qkv_x[M_ROWS*QKV_DIM];
__device__ float g_qkv_y[M_ROWS*QKV_DIM];
__device__ float g_att_x[M_ROWS*C_DIM];
__device__ float g_att_y[M_ROWS*C_DIM];
__device__ __half g_x_hi[M_ROWS*C_DIM],     g_x_lo[M_ROWS*C_DIM];
__device__ __half g_y_hi[M_ROWS*C_DIM],     g_y_lo[M_ROWS*C_DIM];
__device__ __half g_wqkv_hi[QKV_DIM*C_DIM], g_wqkv_lo[QKV_DIM*C_DIM];
__device__ __half g_wproj_hi[C_DIM*C_DIM],  g_wproj_lo[C_DIM*C_DIM];
__device__ __half g_ax_hi[M_ROWS*C_DIM],    g_ax_lo[M_ROWS*C_DIM];
__device__ __half g_ay_hi[M_ROWS*C_DIM],    g_ay_lo[M_ROWS*C_DIM];

// ============================================================
// helpers
// ============================================================
__device__ __forceinline__ uint32_t smem_u32(const void* p) {
    uint32_t a;
    asm("{ .reg .u64 t; cvta.to.shared.u64 t, %1; cvt.u32.u64 %0, t; }"
        : "=r"(a) : "l"(p));
    return a;
}

__device__ __forceinline__ void ldsm_x4(uint32_t addr, uint32_t& r0, uint32_t& r1,
                                        uint32_t& r2, uint32_t& r3) {
    asm volatile("ldmatrix.sync.aligned.m8n8.x4.shared.b16 {%0,%1,%2,%3}, [%4];"
                 : "=r"(r0), "=r"(r1), "=r"(r2), "=r"(r3) : "r"(addr));
}

__device__ __forceinline__ void mma_f16(float* c, const uint32_t* a,
                                        uint32_t b0, uint32_t b1) {
    asm volatile(
        "mma.sync.aligned.m16n8k16.row.col.f32.f16.f16.f32 "
        "{%0,%1,%2,%3}, {%4,%5,%6,%7}, {%8,%9}, {%0,%1,%2,%3};"
        : "+f"(c[0]), "+f"(c[1]), "+f"(c[2]), "+f"(c[3])
        : "r"(a[0]), "r"(a[1]), "r"(a[2]), "r"(a[3]), "r"(b0), "r"(b1));
}

__device__ __forceinline__ void cp_async16(uint32_t saddr, const void* gptr) {
    asm volatile("cp.async.cg.shared.global [%0], [%1], 16;"
                 :: "r"(saddr), "l"(gptr));
}
__device__ __forceinline__ void cp_commit() {
    asm volatile("cp.async.commit_group;" ::: "memory");
}
__device__ __forceinline__ void cp_wait0() { asm volatile("cp.async.wait_group 0;" ::: "memory"); }
__device__ __forceinline__ void cp_wait1() { asm volatile("cp.async.wait_group 1;" ::: "memory"); }
__device__ __forceinline__ void cp_wait2() { asm volatile("cp.async.wait_group 2;" ::: "memory"); }

__device__ __forceinline__ uint32_t pack_h2(__half a, __half b) {
    return ((uint32_t)__half_as_ushort(b) << 16) | (uint32_t)__half_as_ushort(a);
}

// split fp32 float4 -> hi/lo fp16 limb pairs
__device__ __forceinline__ void split4h(float4 v, uint2& hi, uint2& lo) {
    __half h0 = __float2half_rn(v.x);
    __half h1 = __float2half_rn(v.y);
    __half h2 = __float2half_rn(v.z);
    __half h3 = __float2half_rn(v.w);
    __half l0 = __float2half_rn(v.x - __half2float(h0));
    __half l1 = __float2half_rn(v.y - __half2float(h1));
    __half l2 = __float2half_rn(v.z - __half2float(h2));
    __half l3 = __float2half_rn(v.w - __half2float(h3));
    hi.x = pack_h2(h0, h1); hi.y = pack_h2(h2, h3);
    lo.x = pack_h2(l0, l1); lo.y = pack_h2(l2, l3);
}

// fp32 float4 -> fp16 hi only
__device__ __forceinline__ uint2 hi4h(float4 v) {
    return make_uint2(pack_h2(__float2half_rn(v.x), __float2half_rn(v.y)),
                      pack_h2(__float2half_rn(v.z), __float2half_rn(v.w)));
}

// ============================================================
// fp32 -> fp16 limb split kernel (memory-bound pre-pass)
// ============================================================
__global__ __launch_bounds__(256) void split_kernel(
    const float* __restrict__ src, __half* __restrict__ hi,
    __half* __restrict__ lo, int n4)
{
    int i = blockIdx.x * 256 + threadIdx.x;
    if (i < n4) {
        float4 v = ((const float4*)src)[i];
        uint2 h, l;
        split4h(v, h, l);
        ((uint2*)hi)[i] = h;
        ((uint2*)lo)[i] = l;
    }
}

// ============================================================
// split-fp16 mma.sync GEMM, limb inputs.
// Tiles with n0 < npass_lim: 2-pass (AhBh + AlBh); else 1-pass.
// CTA tile 128m x 256n, 8 warps (2m x 4n), warp tile 64x64.
// BK=16, 4-deep cp.async ring, 1 sync/stage.
// ============================================================
#define LDH2 24                        // halves per row (16 + 8 pad)
#define ACH  (128 * LDH2)              // 3072 halves per A limb array
#define BCH  (256 * LDH2)              // 6144 halves per B array
#define STGH2 (2*ACH + BCH)            // 12288 halves per stage
#define STGB  (STGH2 * 2)              // 24576 bytes per stage
#define GEMM_SMEM (4 * STGB)           // 98304

__global__ __launch_bounds__(256, 1) void gemm_mma(
    const __half* __restrict__ Ah0, const __half* __restrict__ Al0,
    const __half* __restrict__ Ah1, const __half* __restrict__ Al1,
    const __half* __restrict__ Bh,
    const float* __restrict__ bias,
    float* __restrict__ C0, float* __restrict__ C1,
    int M, int N, int K, int n_lim1, int npass_lim)
{
    extern __shared__ __align__(16) __half sh[];
    const int tid  = threadIdx.x;
    const int wid  = tid >> 5;
    const int lane = tid & 31;
    const int m0 = blockIdx.y * 128, n0 = blockIdx.x * 256;
    if (blockIdx.z && n0 >= n_lim1) return;   // vy skip for y-QKV
    const bool two_pass = (n0 < npass_lim);
    const int wm = (wid & 1) * 64;
    const int wn = (wid >> 1) * 64;
    const int S  = K / 16;

    const __half* A_h = blockIdx.z ? Ah1 : Ah0;
    const __half* A_l = blockIdx.z ? Al1 : Al0;
    float*        C   = blockIdx.z ? C1  : C0;

    const uint32_t sbase = smem_u32(sh);
    const int ld_row = tid >> 1;
    const int ld_c   = (tid & 1) << 3;

    auto issue_stage = [&](int s, int buf) {
        const int kb = s * 16;
        const uint32_t so = sbase + (uint32_t)buf * STGB;
        const uint32_t ro = (uint32_t)(ld_row * LDH2 + ld_c) * 2u;
        const uint32_t r2 = (uint32_t)((ld_row + 128) * LDH2 + ld_c) * 2u;
        const size_t ga  = (size_t)(m0 + ld_row) * K + kb + ld_c;
        const size_t gb  = (size_t)(n0 + ld_row) * K + kb + ld_c;
        const size_t gb2 = (size_t)(n0 + ld_row + 128) * K + kb + ld_c;
        cp_async16(so + ro,                        A_h + ga);
        if (two_pass)
            cp_async16(so + (uint32_t)(ACH*2) + ro, A_l + ga);
        cp_async16(so + (uint32_t)(2*ACH*2) + ro,  Bh + gb);
        cp_async16(so + (uint32_t)(2*ACH*2) + r2,  Bh + gb2);
    };

    float acc[4][8][4];
#pragma unroll
    for (int i = 0; i < 4; i++)
#pragma unroll
        for (int j = 0; j < 8; j++)
#pragma unroll
            for (int r = 0; r < 4; r++) acc[i][j][r] = 0.f;

    const int a_off = (wm + (lane & 15)) * LDH2 + ((lane >> 4) << 3);
    const int b_off = (wn + ((lane >> 4) << 3) + (lane & 7)) * LDH2 + (((lane >> 3) & 1) << 3);

    issue_stage(0, 0); cp_commit();
    issue_stage(1, 1); cp_commit();
    issue_stage(2, 2); cp_commit();

    for (int s = 0; s < S; s++) {
        if (s + 2 < S)      cp_wait2();
        else if (s + 1 < S) cp_wait1();
        else                cp_wait0();
        __syncthreads();
        if (s + 3 < S) { issue_stage(s + 3, (s + 3) & 3); cp_commit(); }

        const uint32_t stg = sbase + (uint32_t)((s & 3) * STGB);

        uint32_t ah[4][4], bh[8][2], t[4][4];
#pragma unroll
        for (int mt = 0; mt < 4; mt++)
            ldsm_x4(stg + (uint32_t)(a_off + mt * 16 * LDH2) * 2u,
                    ah[mt][0], ah[mt][1], ah[mt][2], ah[mt][3]);
#pragma unroll
        for (int p = 0; p < 4; p++)
            ldsm_x4(stg + (uint32_t)(2*ACH + b_off + p * 16 * LDH2) * 2u,
                    bh[p*2][0], bh[p*2][1], bh[p*2+1][0], bh[p*2+1][1]);

        // pass 1: Ah * Bh
#pragma unroll
        for (int mt = 0; mt < 4; mt++)
#pragma unroll
            for (int nt = 0; nt < 8; nt++)
                mma_f16(acc[mt][nt], ah[mt], bh[nt][0], bh[nt][1]);

        // pass 2: Al * Bh (only for output tiles feeding hi+lo consumers)
        if (two_pass) {
#pragma unroll
            for (int mt = 0; mt < 4; mt++)
                ldsm_x4(stg + (uint32_t)(ACH + a_off + mt * 16 * LDH2) * 2u,
                        t[mt][0], t[mt][1], t[mt][2], t[mt][3]);
#pragma unroll
            for (int mt = 0; mt < 4; mt++)
#pragma unroll
                for (int nt = 0; nt < 8; nt++)
                    mma_f16(acc[mt][nt], t[mt], bh[nt][0], bh[nt][1]);
        }
    }

    // ---- epilogue: fp32 (+bias) ----
#pragma unroll
    for (int mt = 0; mt < 4; mt++) {
        int row0 = m0 + wm + mt * 16 + (lane >> 2);
#pragma unroll
        for (int nt = 0; nt < 8; nt++) {
            int col = n0 + wn + nt * 8 + (lane & 3) * 2;
            float b0 = 0.f, b1 = 0.f;
            if (bias) { b0 = __ldg(bias + col); b1 = __ldg(bias + col + 1); }
            float2 v0 = make_float2(acc[mt][nt][0] + b0, acc[mt][nt][1] + b1);
            float2 v1 = make_float2(acc[mt][nt][2] + b0, acc[mt][nt][3] + b1);
            *(float2*)(C + (size_t)row0 * N + col)       = v0;
            *(float2*)(C + (size_t)(row0 + 8) * N + col) = v1;
        }
    }
}

// ============================================================
// Dual-softmax flash attention, fp16 hi-only operands.
// S = Qh Kh (1-pass), O = Ph Vh (1-pass).
// Double-buffered K/V, register prefetch, 1 sync/iter.
// ATT_SMEM padded above 116736 B to force 1 CTA/SM (R9 lesson).
// ============================================================
#define AQS 72
#define OQ1H 0
#define OQ2H (128*AQS)
#define OKV  (2*128*AQS)
#define KVH  (2*64*AQS)                     // Kh, Vh
#define ATT_SMEM 117760                     // padded: > 233472/2 -> 1 CTA/SM

__global__ __launch_bounds__(256, 1) void attention_mma()
{
    extern __shared__ __align__(16) __half sh[];
    const uint32_t sb = smem_u32(sh);
    const int tid  = threadIdx.x;
    const int wid  = tid >> 5;
    const int lane = tid & 31;
    const int wm   = wid * 16;

    const int b    = blockIdx.z;
    const int h    = blockIdx.y >> 1;
    const int pair = blockIdx.y & 1;
    const int q0   = blockIdx.x * 128;

    const float* bx = g_qkv_x + (size_t)b * SEQ * QKV_DIM;
    const float* by = g_qkv_y + (size_t)b * SEQ * QKV_DIM;
    const int hoff  = h * HD;

    const float *Q1src, *Q2src, *Ksrc;
    float* outp;
    if (pair == 0) { Q1src = bx + C_DIM; Q2src = by;  Ksrc = bx + 2 * C_DIM; outp = g_att_x; }
    else           { Q1src = by + C_DIM; Q2src = bx;  Ksrc = by + 2 * C_DIM; outp = g_att_y; }
    const float* Vsrc = bx + 3 * C_DIM;   // vy = vx in the reference

    const int v_jp = tid & 31;
    const int v_d0 = (tid >> 5) * 8;

    // ---- load Q tiles as pre-scaled fp16 hi ----
#pragma unroll
    for (int u = 0; u < 8; u++) {
        int idx = u * 256 + tid;
        int row = idx >> 4;
        int c4  = (idx & 15) << 2;
        float4 v1 = *(const float4*)(Q1src + (size_t)(q0 + row) * QKV_DIM + hoff + c4);
        float4 v2 = *(const float4*)(Q2src + (size_t)(q0 + row) * QKV_DIM + hoff + c4);
        v1.x *= 0.125f; v1.y *= 0.125f; v1.z *= 0.125f; v1.w *= 0.125f;
        v2.x *= -0.125f; v2.y *= -0.125f; v2.z *= -0.125f; v2.w *= -0.125f;
        int off = row * AQS + c4;
        *(uint2*)(sh + OQ1H + off) = hi4h(v1);
        *(uint2*)(sh + OQ2H + off) = hi4h(v2);
    }

    // ---- load KV tile 0 (K: [j][d] hi; V: [d][j] hi, transposed store) ----
    {
#pragma unroll
        for (int u = 0; u < 4; u++) {
            int idx = u * 256 + tid;
            int row = idx >> 4;
            int c4  = (idx & 15) << 2;
            float4 kv = *(const float4*)(Ksrc + (size_t)row * QKV_DIM + hoff + c4);
            *(uint2*)(sh + OKV + row * AQS + c4) = hi4h(kv);
        }
        const float* v0p = Vsrc + (size_t)(2 * v_jp)     * QKV_DIM + hoff + v_d0;
        const float* v1p = Vsrc + (size_t)(2 * v_jp + 1) * QKV_DIM + hoff + v_d0;
        float4 va0 = *(const float4*)(v0p);
        float4 va1 = *(const float4*)(v0p + 4);
        float4 vb0 = *(const float4*)(v1p);
        float4 vb1 = *(const float4*)(v1p + 4);
        float f0[8] = {va0.x, va0.y, va0.z, va0.w, va1.x, va1.y, va1.z, va1.w};
        float f1[8] = {vb0.x, vb0.y, vb0.z, vb0.w, vb1.x, vb1.y, vb1.z, vb1.w};
#pragma unroll
        for (int i = 0; i < 8; i++)
            *(uint32_t*)(sh + OKV + 64*AQS + (v_d0 + i) * AQS + 2 * v_jp) =
                pack_h2(__float2half_rn(f0[i]), __float2half_rn(f1[i]));
    }
    __syncthreads();

    float o1[8][4], o2[8][4];
#pragma unroll
    for (int d = 0; d < 8; d++)
#pragma unroll
        for (int r = 0; r < 4; r++) { o1[d][r] = 0.f; o2[d][r] = 0.f; }
    float m1lo = -1e30f, m1hi = -1e30f, l1lo = 0.f, l1hi = 0.f;
    float m2lo = -1e30f, m2hi = -1e30f, l2lo = 0.f, l2hi = 0.f;

    const uint32_t a_base = (uint32_t)((wm + (lane & 15)) * AQS + ((lane >> 4) << 3)) * 2u;
    const uint32_t b_base = (uint32_t)((((lane >> 4) << 3) + (lane & 7)) * AQS
                                       + (((lane >> 3) & 1) << 3)) * 2u;

    for (int kt = 0; kt < 16; kt++) {
        const int cur = kt & 1;
        const uint32_t kvb = (uint32_t)(OKV + cur * KVH) * 2u;

        // ---- prefetch next KV tile into registers ----
        float4 kpre[4], vpre[4];
        if (kt < 15) {
            const int j0n = (kt + 1) * 64;
#pragma unroll
            for (int u = 0; u < 4; u++) {
                int idx = u * 256 + tid;
                int row = idx >> 4;
                int c4  = (idx & 15) << 2;
                kpre[u] = *(const float4*)(Ksrc + (size_t)(j0n + row) * QKV_DIM + hoff + c4);
            }
            const float* v0p = Vsrc + (size_t)(j0n + 2 * v_jp)     * QKV_DIM + hoff + v_d0;
            const float* v1p = Vsrc + (size_t)(j0n + 2 * v_jp + 1) * QKV_DIM + hoff + v_d0;
            vpre[0] = *(const float4*)(v0p);
            vpre[1] = *(const float4*)(v0p + 4);
            vpre[2] = *(const float4*)(v1p);
            vpre[3] = *(const float4*)(v1p + 4);
        }

        // ---- S = Q K^T (1-pass: Qh*Kh), stream-interleaved ----
        float s1[8][4], s2[8][4];
#pragma unroll
        for (int n = 0; n < 8; n++)
#pragma unroll
            for (int r = 0; r < 4; r++) { s1[n][r] = 0.f; s2[n][r] = 0.f; }

#pragma unroll
        for (int ks = 0; ks < 4; ks++) {
            const uint32_t kofs = (uint32_t)(ks * 16) * 2u;
            uint32_t a1h[4], a2h[4];
            ldsm_x4(sb + OQ1H*2u + a_base + kofs, a1h[0], a1h[1], a1h[2], a1h[3]);
            ldsm_x4(sb + OQ2H*2u + a_base + kofs, a2h[0], a2h[1], a2h[2], a2h[3]);
#pragma unroll
            for (int jt = 0; jt < 4; jt++) {
                uint32_t rb = sb + kvb + b_base + (uint32_t)(jt * 16 * AQS) * 2u + kofs;
                uint32_t bh[2][2];
                ldsm_x4(rb, bh[0][0], bh[0][1], bh[1][0], bh[1][1]);
#pragma unroll
                for (int q = 0; q < 2; q++) {
                    int nt = jt * 2 + q;
                    mma_f16(s1[nt], a1h, bh[q][0], bh[q][1]);
                    mma_f16(s2[nt], a2h, bh[q][0], bh[q][1]);
                }
            }
        }

        // ---- store prefetched tile into the other buffer ----
        if (kt < 15) {
            const int nb = OKV + (cur ^ 1) * KVH;
#pragma unroll
            for (int u = 0; u < 4; u++) {
                int idx = u * 256 + tid;
                int row = idx >> 4;
                int c4  = (idx & 15) << 2;
                *(uint2*)(sh + nb + row * AQS + c4) = hi4h(kpre[u]);
            }
            float f0[8] = {vpre[0].x, vpre[0].y, vpre[0].z, vpre[0].w,
                           vpre[1].x, vpre[1].y, vpre[1].z, vpre[1].w};
            float f1[8] = {vpre[2].x, vpre[2].y, vpre[2].z, vpre[2].w,
                           vpre[3].x, vpre[3].y, vpre[3].z, vpre[3].w};
#pragma unroll
            for (int i = 0; i < 8; i++)
                *(uint32_t*)(sh + nb + 64*AQS + (v_d0 + i) * AQS + 2 * v_jp) =
                    pack_h2(__float2half_rn(f0[i]), __float2half_rn(f1[i]));
        }

        // ---- online softmax (per stream), P as fp16 hi ----
        uint32_t p1h[8][2], p2h[8][2];
        {
            float mxlo = -1e30f, mxhi = -1e30f;
#pragma unroll
            for (int n = 0; n < 8; n++) {
                mxlo = fmaxf(mxlo, fmaxf(s1[n][0], s1[n][1]));
                mxhi = fmaxf(mxhi, fmaxf(s1[n][2], s1[n][3]));
            }
            mxlo = fmaxf(mxlo, __shfl_xor_sync(0xffffffffu, mxlo, 1));
            mxlo = fmaxf(mxlo, __shfl_xor_sync(0xffffffffu, mxlo, 2));
            mxhi = fmaxf(mxhi, __shfl_xor_sync(0xffffffffu, mxhi, 1));
            mxhi = fmaxf(mxhi, __shfl_xor_sync(0xffffffffu, mxhi, 2));
            float mnlo = fmaxf(m1lo, mxlo), mnhi = fmaxf(m1hi, mxhi);
            float clo = __expf(m1lo - mnlo), chi = __expf(m1hi - mnhi);
            m1lo = mnlo; m1hi = mnhi;
            float sl = 0.f, shh = 0.f;
#pragma unroll
            for (int n = 0; n < 8; n++) {
                float p0 = __expf(s1[n][0] - mnlo);
                float p1 = __expf(s1[n][1] - mnlo);
                float p2 = __expf(s1[n][2] - mnhi);
                float p3 = __expf(s1[n][3] - mnhi);
                sl += p0 + p1; shh += p2 + p3;
                p1h[n][0] = pack_h2(__float2half_rn(p0), __float2half_rn(p1));
                p1h[n][1] = pack_h2(__float2half_rn(p2), __float2half_rn(p3));
            }
            sl  += __shfl_xor_sync(0xffffffffu, sl, 1);
            sl  += __shfl_xor_sync(0xffffffffu, sl, 2);
            shh += __shfl_xor_sync(0xffffffffu, shh, 1);
            shh += __shfl_xor_sync(0xffffffffu, shh, 2);
            l1lo = l1lo * clo + sl; l1hi = l1hi * chi + shh;
#pragma unroll
            for (int d = 0; d < 8; d++) {
                o1[d][0] *= clo; o1[d][1] *= clo;
                o1[d][2] *= chi; o1[d][3] *= chi;
            }
        }
        {
            float mxlo = -1e30f, mxhi = -1e30f;
#pragma unroll
            for (int n = 0; n < 8; n++) {
                mxlo = fmaxf(mxlo, fmaxf(s2[n][0], s2[n][1]));
                mxhi = fmaxf(mxhi, fmaxf(s2[n][2], s2[n][3]));
            }
            mxlo = fmaxf(mxlo, __shfl_xor_sync(0xffffffffu, mxlo, 1));
            mxlo = fmaxf(mxlo, __shfl_xor_sync(0xffffffffu, mxlo, 2));
            mxhi = fmaxf(mxhi, __shfl_xor_sync(0xffffffffu, mxhi, 1));
            mxhi = fmaxf(mxhi, __shfl_xor_sync(0xffffffffu, mxhi, 2));
            float mnlo = fmaxf(m2lo, mxlo), mnhi = fmaxf(m2hi, mxhi);
            float clo = __expf(m2lo - mnlo), chi = __expf(m2hi - mnhi);
            m2lo = mnlo; m2hi = mnhi;
            float sl = 0.f, shh = 0.f;
#pragma unroll
            for (int n = 0; n < 8; n++) {
                float p0 = __expf(s2[n][0] - mnlo);
                float p1 = __expf(s2[n][1] - mnlo);
                float p2 = __expf(s2[n][2] - mnhi);
                float p3 = __expf(s2[n][3] - mnhi);
                sl += p0 + p1; shh += p2 + p3;
                p2h[n][0] = pack_h2(__float2half_rn(p0), __float2half_rn(p1));
                p2h[n][1] = pack_h2(__float2half_rn(p2), __float2half_rn(p3));
            }
            sl  += __shfl_xor_sync(0xffffffffu, sl, 1);
            sl  += __shfl_xor_sync(0xffffffffu, sl, 2);
            shh += __shfl_xor_sync(0xffffffffu, shh, 1);
            shh += __shfl_xor_sync(0xffffffffu, shh, 2);
            l2lo = l2lo * clo + sl; l2hi = l2hi * chi + shh;
#pragma unroll
            for (int d = 0; d < 8; d++) {
                o2[d][0] *= clo; o2[d][1] *= clo;
                o2[d][2] *= chi; o2[d][3] *= chi;
            }
        }

        // ---- O += P V (1-pass: Ph*Vh) ----
#pragma unroll
        for (int ks = 0; ks < 4; ks++) {
            uint32_t a1f[4] = { p1h[2*ks][0], p1h[2*ks][1], p1h[2*ks+1][0], p1h[2*ks+1][1] };
            uint32_t a2f[4] = { p2h[2*ks][0], p2h[2*ks][1], p2h[2*ks+1][0], p2h[2*ks+1][1] };
            const uint32_t kofs = (uint32_t)(ks * 16) * 2u;
#pragma unroll
            for (int dt2 = 0; dt2 < 4; dt2++) {
                uint32_t rb = sb + kvb + (uint32_t)(64*AQS)*2u + b_base
                            + (uint32_t)(dt2 * 16 * AQS) * 2u + kofs;
                uint32_t vh[2][2];
                ldsm_x4(rb, vh[0][0], vh[0][1], vh[1][0], vh[1][1]);
#pragma unroll
                for (int q = 0; q < 2; q++) {
                    int dt = dt2 * 2 + q;
                    mma_f16(o1[dt], a1f, vh[q][0], vh[q][1]);
                    mma_f16(o2[dt], a2f, vh[q][0], vh[q][1]);
                }
            }
        }

        if (kt < 15) __syncthreads();
    }

    // ---- epilogue: out = O1/l1 + O2/l2 (fp32) ----
    const float i1lo = 1.f / l1lo, i1hi = 1.f / l1hi;
    const float i2lo = 1.f / l2lo, i2hi = 1.f / l2hi;
    float* obase = outp + (size_t)b * SEQ * C_DIM;
    const int r0 = q0 + wm + (lane >> 2);
    const int cb = hoff + (lane & 3) * 2;
#pragma unroll
    for (int dt = 0; dt < 8; dt++) {
        int col = cb + dt * 8;
        float2 vlo = make_float2(o1[dt][0] * i1lo + o2[dt][0] * i2lo,
                                 o1[dt][1] * i1lo + o2[dt][1] * i2lo);
        float2 vhi = make_float2(o1[dt][2] * i1hi + o2[dt][2] * i2hi,
                                 o1[dt][3] * i1hi + o2[dt][3] * i2hi);
        *(float2*)(obase + (size_t)r0 * C_DIM + col)       = vlo;
        *(float2*)(obase + (size_t)(r0 + 8) * C_DIM + col) = vhi;
    }
}

// ============================================================
extern "C" void kernel_launch(void* const* d_in, const int* in_sizes, int n_in,
                              void* d_out, int out_size)
{
    const float* x      = (const float*)d_in[0];
    const float* y      = (const float*)d_in[1];
    const float* w_qkv  = (const float*)d_in[2];
    const float* w_proj = (const float*)d_in[3];
    const float* b_proj = (const float*)d_in[4];
    float* out = (float*)d_out;

    float *qx, *qy, *ax, *ay;
    __half *xh, *xl, *yh, *yl, *wqh, *wql, *wph, *wpl;
    __half *axh, *axl, *ayh, *ayl;
    cudaGetSymbolAddress((void**)&qx,  g_qkv_x);
    cudaGetSymbolAddress((void**)&qy,  g_qkv_y);
    cudaGetSymbolAddress((void**)&ax,  g_att_x);
    cudaGetSymbolAddress((void**)&ay,  g_att_y);
    cudaGetSymbolAddress((void**)&xh,  g_x_hi);     cudaGetSymbolAddress((void**)&xl,  g_x_lo);
    cudaGetSymbolAddress((void**)&yh,  g_y_hi);     cudaGetSymbolAddress((void**)&yl,  g_y_lo);
    cudaGetSymbolAddress((void**)&wqh, g_wqkv_hi);  cudaGetSymbolAddress((void**)&wql, g_wqkv_lo);
    cudaGetSymbolAddress((void**)&wph, g_wproj_hi); cudaGetSymbolAddress((void**)&wpl, g_wproj_lo);
    cudaGetSymbolAddress((void**)&axh, g_ax_hi);    cudaGetSymbolAddress((void**)&axl, g_ax_lo);
    cudaGetSymbolAddress((void**)&ayh, g_ay_hi);    cudaGetSymbolAddress((void**)&ayl, g_ay_lo);

    cudaFuncSetAttribute(gemm_mma,
                         cudaFuncAttributeMaxDynamicSharedMemorySize, GEMM_SMEM);
    cudaFuncSetAttribute(attention_mma,
                         cudaFuncAttributeMaxDynamicSharedMemorySize, ATT_SMEM);

    // 0) fp32 -> fp16 limb pre-splits
    split_kernel<<<(M_ROWS*C_DIM/4 + 255)/256, 256>>>(x, xh, xl, M_ROWS*C_DIM/4);
    split_kernel<<<(M_ROWS*C_DIM/4 + 255)/256, 256>>>(y, yh, yl, M_ROWS*C_DIM/4);
    split_kernel<<<(QKV_DIM*C_DIM/4 + 255)/256, 256>>>(w_qkv, wqh, wql, QKV_DIM*C_DIM/4);
    split_kernel<<<(C_DIM*C_DIM/4 + 255)/256, 256>>>(w_proj, wph, wpl, C_DIM*C_DIM/4);

    // 1) QKV projections: qo/q tiles (n<1536) 2-pass, k/v tiles 1-pass;
    //    y-branch skips unused vy (n >= 2304)
    dim3 g1(QKV_DIM / 256, M_ROWS / 128, 2);
    gemm_mma<<<g1, 256, GEMM_SMEM>>>(xh, xl, yh, yl, wqh, nullptr,
                                     qx, qy, M_ROWS, QKV_DIM, C_DIM, 2304, 1536);

    // 2) fused dual-softmax attention (fp16 hi operands, 1-pass S and PV)
    attention_mma<<<dim3(SEQ / 128, HEADS * 2, BATCH), 256, ATT_SMEM>>>();

    // 2b) split attention outputs to fp16 limbs for proj
    split_kernel<<<(M_ROWS*C_DIM/4 + 255)/256, 256>>>(ax, axh, axl, M_ROWS*C_DIM/4);
    split_kernel<<<(M_ROWS*C_DIM/4 + 255)/256, 256>>>(ay, ayh, ayl, M_ROWS*C_DIM/4);

    // 3) output projections + bias, 2-pass fp16 everywhere
    dim3 g2(C_DIM / 256, M_ROWS / 128, 2);
    gemm_mma<<<g2, 256, GEMM_SMEM>>>(axh, axl, ayh, ayl, wph, b_proj,
                                     out, out + (size_t)M_ROWS * C_DIM,
                                     M_ROWS, C_DIM, C_DIM, C_DIM, C_DIM);
}

// round 13
// speedup vs baseline: 2.3432x; 1.3651x over previous
#include <cuda_runtime.h>
#include <cuda_fp16.h>
#include <cstdint>

#define C_DIM   768
#define QKV_DIM 3072
#define BATCH   4
#define SEQ     1024
#define HEADS   12
#define HD      64
#define M_ROWS  (BATCH*SEQ)   // 4096

// -------- scratch (allocation-free: device globals, all fp16) --------
__device__ __half g_x_h[M_ROWS*C_DIM];
__device__ __half g_y_h[M_ROWS*C_DIM];
__device__ __half g_wqkv_h[QKV_DIM*C_DIM];
__device__ __half g_wproj_h[C_DIM*C_DIM];
__device__ __half g_qkvx_h[M_ROWS*QKV_DIM];
__device__ __half g_qkvy_h[M_ROWS*QKV_DIM];
__device__ __half g_attx_h[M_ROWS*C_DIM];
__device__ __half g_atty_h[M_ROWS*C_DIM];

// ============================================================
// helpers
// ============================================================
__device__ __forceinline__ uint32_t smem_u32(const void* p) {
    uint32_t a;
    asm("{ .reg .u64 t; cvta.to.shared.u64 t, %1; cvt.u32.u64 %0, t; }"
        : "=r"(a) : "l"(p));
    return a;
}

__device__ __forceinline__ void ldsm_x4(uint32_t addr, uint32_t& r0, uint32_t& r1,
                                        uint32_t& r2, uint32_t& r3) {
    asm volatile("ldmatrix.sync.aligned.m8n8.x4.shared.b16 {%0,%1,%2,%3}, [%4];"
                 : "=r"(r0), "=r"(r1), "=r"(r2), "=r"(r3) : "r"(addr));
}

__device__ __forceinline__ void ldsm_x4_t(uint32_t addr, uint32_t& r0, uint32_t& r1,
                                          uint32_t& r2, uint32_t& r3) {
    asm volatile("ldmatrix.sync.aligned.m8n8.x4.trans.shared.b16 {%0,%1,%2,%3}, [%4];"
                 : "=r"(r0), "=r"(r1), "=r"(r2), "=r"(r3) : "r"(addr));
}

__device__ __forceinline__ void mma_f16(float* c, const uint32_t* a,
                                        uint32_t b0, uint32_t b1) {
    asm volatile(
        "mma.sync.aligned.m16n8k16.row.col.f32.f16.f16.f32 "
        "{%0,%1,%2,%3}, {%4,%5,%6,%7}, {%8,%9}, {%0,%1,%2,%3};"
        : "+f"(c[0]), "+f"(c[1]), "+f"(c[2]), "+f"(c[3])
        : "r"(a[0]), "r"(a[1]), "r"(a[2]), "r"(a[3]), "r"(b0), "r"(b1));
}

__device__ __forceinline__ void cp_async16(uint32_t saddr, const void* gptr) {
    asm volatile("cp.async.cg.shared.global [%0], [%1], 16;"
                 :: "r"(saddr), "l"(gptr));
}
__device__ __forceinline__ void cp_commit() {
    asm volatile("cp.async.commit_group;" ::: "memory");
}
__device__ __forceinline__ void cp_wait0() { asm volatile("cp.async.wait_group 0;" ::: "memory"); }
__device__ __forceinline__ void cp_wait1() { asm volatile("cp.async.wait_group 1;" ::: "memory"); }
__device__ __forceinline__ void cp_wait2() { asm volatile("cp.async.wait_group 2;" ::: "memory"); }

__device__ __forceinline__ uint32_t pack_h2(__half a, __half b) {
    return ((uint32_t)__half_as_ushort(b) << 16) | (uint32_t)__half_as_ushort(a);
}

// fp32 float4 -> fp16 x4
__device__ __forceinline__ uint2 hi4h(float4 v) {
    return make_uint2(pack_h2(__float2half_rn(v.x), __float2half_rn(v.y)),
                      pack_h2(__float2half_rn(v.z), __float2half_rn(v.w)));
}

// ============================================================
// fp32 -> fp16 convert kernel (memory-bound pre-pass)
// ============================================================
__global__ __launch_bounds__(256) void cvt_kernel(
    const float* __restrict__ src, __half* __restrict__ dst, int n4)
{
    int i = blockIdx.x * 256 + threadIdx.x;
    if (i < n4) {
        float4 v = ((const float4*)src)[i];
        ((uint2*)dst)[i] = hi4h(v);
    }
}

// ============================================================
// fp16 mma.sync GEMM (fp32 accum). 1-pass.
// CTA tile 128m x 256n, 8 warps (2m x 4n), warp tile 64x64.
// BK=16, 4-deep cp.async ring, 1 sync/stage.
// Output: fp32 (+bias) if Cf0, else fp16.
// ============================================================
#define LDH2 24                        // halves per row (16 + 8 pad)
#define ACH  (128 * LDH2)              // 3072 halves per A array
#define BCH  (256 * LDH2)              // 6144 halves per B array
#define STGH2 (ACH + BCH)              // 9216 halves per stage
#define STGB  (STGH2 * 2)              // 18432 bytes per stage
#define GEMM_SMEM (4 * STGB)           // 73728

__global__ __launch_bounds__(256, 1) void gemm_mma(
    const __half* __restrict__ A0, const __half* __restrict__ A1,
    const __half* __restrict__ B,
    const float* __restrict__ bias,
    float* __restrict__ Cf0, float* __restrict__ Cf1,
    __half* __restrict__ Ch0, __half* __restrict__ Ch1,
    int M, int N, int K, int n_lim1)
{
    extern __shared__ __align__(16) __half sh[];
    const int tid  = threadIdx.x;
    const int wid  = tid >> 5;
    const int lane = tid & 31;
    const int m0 = blockIdx.y * 128, n0 = blockIdx.x * 256;
    if (blockIdx.z && n0 >= n_lim1) return;   // vy skip for y-QKV
    const int wm = (wid & 1) * 64;
    const int wn = (wid >> 1) * 64;
    const int S  = K / 16;

    const __half* A = blockIdx.z ? A1 : A0;

    const uint32_t sbase = smem_u32(sh);
    const int ld_row = tid >> 1;
    const int ld_c   = (tid & 1) << 3;

    auto issue_stage = [&](int s, int buf) {
        const int kb = s * 16;
        const uint32_t so = sbase + (uint32_t)buf * STGB;
        const uint32_t ro = (uint32_t)(ld_row * LDH2 + ld_c) * 2u;
        const uint32_t r2 = (uint32_t)((ld_row + 128) * LDH2 + ld_c) * 2u;
        cp_async16(so + ro, A + (size_t)(m0 + ld_row) * K + kb + ld_c);
        cp_async16(so + (uint32_t)(ACH*2) + ro, B + (size_t)(n0 + ld_row) * K + kb + ld_c);
        cp_async16(so + (uint32_t)(ACH*2) + r2, B + (size_t)(n0 + ld_row + 128) * K + kb + ld_c);
    };

    float acc[4][8][4];
#pragma unroll
    for (int i = 0; i < 4; i++)
#pragma unroll
        for (int j = 0; j < 8; j++)
#pragma unroll
            for (int r = 0; r < 4; r++) acc[i][j][r] = 0.f;

    const int a_off = (wm + (lane & 15)) * LDH2 + ((lane >> 4) << 3);
    const int b_off = (wn + ((lane >> 4) << 3) + (lane & 7)) * LDH2 + (((lane >> 3) & 1) << 3);

    issue_stage(0, 0); cp_commit();
    issue_stage(1, 1); cp_commit();
    issue_stage(2, 2); cp_commit();

    for (int s = 0; s < S; s++) {
        if (s + 2 < S)      cp_wait2();
        else if (s + 1 < S) cp_wait1();
        else                cp_wait0();
        __syncthreads();
        if (s + 3 < S) { issue_stage(s + 3, (s + 3) & 3); cp_commit(); }

        const uint32_t stg = sbase + (uint32_t)((s & 3) * STGB);

        uint32_t ah[4][4], bh[8][2];
#pragma unroll
        for (int mt = 0; mt < 4; mt++)
            ldsm_x4(stg + (uint32_t)(a_off + mt * 16 * LDH2) * 2u,
                    ah[mt][0], ah[mt][1], ah[mt][2], ah[mt][3]);
#pragma unroll
        for (int p = 0; p < 4; p++)
            ldsm_x4(stg + (uint32_t)(ACH + b_off + p * 16 * LDH2) * 2u,
                    bh[p*2][0], bh[p*2][1], bh[p*2+1][0], bh[p*2+1][1]);

#pragma unroll
        for (int mt = 0; mt < 4; mt++)
#pragma unroll
            for (int nt = 0; nt < 8; nt++)
                mma_f16(acc[mt][nt], ah[mt], bh[nt][0], bh[nt][1]);
    }

    // ---- epilogue ----
    if (Cf0) {
        float* C = blockIdx.z ? Cf1 : Cf0;
#pragma unroll
        for (int mt = 0; mt < 4; mt++) {
            int row0 = m0 + wm + mt * 16 + (lane >> 2);
#pragma unroll
            for (int nt = 0; nt < 8; nt++) {
                int col = n0 + wn + nt * 8 + (lane & 3) * 2;
                float b0 = 0.f, b1 = 0.f;
                if (bias) { b0 = __ldg(bias + col); b1 = __ldg(bias + col + 1); }
                float2 v0 = make_float2(acc[mt][nt][0] + b0, acc[mt][nt][1] + b1);
                float2 v1 = make_float2(acc[mt][nt][2] + b0, acc[mt][nt][3] + b1);
                *(float2*)(C + (size_t)row0 * N + col)       = v0;
                *(float2*)(C + (size_t)(row0 + 8) * N + col) = v1;
            }
        }
    } else {
        __half* C = blockIdx.z ? Ch1 : Ch0;
#pragma unroll
        for (int mt = 0; mt < 4; mt++) {
            int row0 = m0 + wm + mt * 16 + (lane >> 2);
#pragma unroll
            for (int nt = 0; nt < 8; nt++) {
                int col = n0 + wn + nt * 8 + (lane & 3) * 2;
                *(uint32_t*)(C + (size_t)row0 * N + col) =
                    pack_h2(__float2half_rn(acc[mt][nt][0]), __float2half_rn(acc[mt][nt][1]));
                *(uint32_t*)(C + (size_t)(row0 + 8) * N + col) =
                    pack_h2(__float2half_rn(acc[mt][nt][2]), __float2half_rn(acc[mt][nt][3]));
            }
        }
    }
}

// ============================================================
// Dual-softmax flash attention, pure fp16 operands (fp32 accum).
// Q/K/V via cp.async; scale applied post-MMA (exact power of 2);
// V row-major [j][d], fragments via ldsm.trans (R6-verified).
// ATT_SMEM padded above 116736 B to force 1 CTA/SM (R9 lesson).
// ============================================================
#define AQS 72
#define OQ1 0
#define OQ2 (128*AQS)
#define OKV (2*128*AQS)
#define KVB (2*64*AQS)                  // per buffer: K, V
#define ATT_SMEM 117760                 // padded: > 233472/2 -> 1 CTA/SM

__global__ __launch_bounds__(256, 1) void attention_mma()
{
    extern __shared__ __align__(16) __half sh[];
    const uint32_t sb = smem_u32(sh);
    const int tid  = threadIdx.x;
    const int wid  = tid >> 5;
    const int lane = tid & 31;
    const int wm   = wid * 16;

    const int b    = blockIdx.z;
    const int h    = blockIdx.y >> 1;
    const int pair = blockIdx.y & 1;
    const int q0   = blockIdx.x * 128;
    const int hoff = h * HD;

    const __half* bx = g_qkvx_h + (size_t)b * SEQ * QKV_DIM;
    const __half* by = g_qkvy_h + (size_t)b * SEQ * QKV_DIM;

    const __half *Q1src, *Q2src, *Ksrc;
    __half* outp;
    if (pair == 0) { Q1src = bx + C_DIM; Q2src = by;  Ksrc = bx + 2 * C_DIM; outp = g_attx_h; }
    else           { Q1src = by + C_DIM; Q2src = bx;  Ksrc = by + 2 * C_DIM; outp = g_atty_h; }
    const __half* Vsrc = bx + 3 * C_DIM;   // vy = vx in the reference
    Q1src += hoff; Q2src += hoff; Ksrc += hoff; Vsrc += hoff;

    // ---- issue Q tiles (one-time, 8 cp.async/thread) ----
    {
        const __half* qs[2] = { Q1src, Q2src };
#pragma unroll
        for (int a = 0; a < 2; a++)
#pragma unroll
            for (int j = 0; j < 4; j++) {
                int cid = tid + j * 256;         // 0..1023
                int row = cid >> 3;              // 0..127
                int c8  = (cid & 7) << 3;        // 0..56
                cp_async16(sb + (uint32_t)(a * 128 * AQS + row * AQS + c8) * 2u,
                           qs[a] + (size_t)(q0 + row) * QKV_DIM + c8);
            }
    }

    // KV tile: 64 rows x 64 halves per tensor -> 512 slots -> 2/thread/tensor
    auto issue_kv = [&](int kt, int buf) {
        const int j0 = kt * 64;
        const int nb = OKV + buf * KVB;
#pragma unroll
        for (int j = 0; j < 2; j++) {
            int cid = tid + j * 256;             // 0..511
            int row = cid >> 3;                  // 0..63
            int c8  = (cid & 7) << 3;            // 0..56
            cp_async16(sb + (uint32_t)(nb + row * AQS + c8) * 2u,
                       Ksrc + (size_t)(j0 + row) * QKV_DIM + c8);
            cp_async16(sb + (uint32_t)(nb + 64 * AQS + row * AQS + c8) * 2u,
                       Vsrc + (size_t)(j0 + row) * QKV_DIM + c8);
        }
    };

    issue_kv(0, 0);
    cp_commit();   // group 0: Q + KV tile 0

    float o1[8][4], o2[8][4];
#pragma unroll
    for (int d = 0; d < 8; d++)
#pragma unroll
        for (int r = 0; r < 4; r++) { o1[d][r] = 0.f; o2[d][r] = 0.f; }
    float m1lo = -1e30f, m1hi = -1e30f, l1lo = 0.f, l1hi = 0.f;
    float m2lo = -1e30f, m2hi = -1e30f, l2lo = 0.f, l2hi = 0.f;

    const uint32_t a_base = (uint32_t)((wm + (lane & 15)) * AQS + ((lane >> 4) << 3)) * 2u;
    const uint32_t b_base = (uint32_t)((((lane >> 4) << 3) + (lane & 7)) * AQS
                                       + (((lane >> 3) & 1) << 3)) * 2u;
    const uint32_t v_base = (uint32_t)(((((lane >> 3) & 1) << 3) + (lane & 7)) * AQS
                                       + ((lane >> 4) << 3)) * 2u;

    for (int kt = 0; kt < 16; kt++) {
        const uint32_t kvb = (uint32_t)(OKV + (kt & 1) * KVB) * 2u;

        if (kt < 15) { issue_kv(kt + 1, (kt + 1) & 1); cp_commit(); cp_wait1(); }
        else         { cp_wait0(); }
        __syncthreads();

        // ---- S = Q K^T (fp16 x fp16 -> fp32) ----
        float s1[8][4], s2[8][4];
#pragma unroll
        for (int n = 0; n < 8; n++)
#pragma unroll
            for (int r = 0; r < 4; r++) { s1[n][r] = 0.f; s2[n][r] = 0.f; }

#pragma unroll
        for (int ks = 0; ks < 4; ks++) {
            const uint32_t kofs = (uint32_t)(ks * 16) * 2u;
            uint32_t a1h[4], a2h[4];
            ldsm_x4(sb + (uint32_t)(OQ1*2) + a_base + kofs, a1h[0], a1h[1], a1h[2], a1h[3]);
            ldsm_x4(sb + (uint32_t)(OQ2*2) + a_base + kofs, a2h[0], a2h[1], a2h[2], a2h[3]);
#pragma unroll
            for (int jt = 0; jt < 4; jt++) {
                uint32_t rb = sb + kvb + b_base + (uint32_t)(jt * 16 * AQS) * 2u + kofs;
                uint32_t bh[2][2];
                ldsm_x4(rb, bh[0][0], bh[0][1], bh[1][0], bh[1][1]);
#pragma unroll
                for (int q = 0; q < 2; q++) {
                    int nt = jt * 2 + q;
                    mma_f16(s1[nt], a1h, bh[q][0], bh[q][1]);
                    mma_f16(s2[nt], a2h, bh[q][0], bh[q][1]);
                }
            }
        }

        // scale: S1 *= hd^-0.5, S2 *= -hd^-0.5 (exact powers of two)
#pragma unroll
        for (int n = 0; n < 8; n++)
#pragma unroll
            for (int r = 0; r < 4; r++) {
                s1[n][r] *=  0.125f;
                s2[n][r] *= -0.125f;
            }

        // ---- online softmax (per stream), P as fp16 ----
        uint32_t p1h[8][2], p2h[8][2];
        {
            float mxlo = -1e30f, mxhi = -1e30f;
#pragma unroll
            for (int n = 0; n < 8; n++) {
                mxlo = fmaxf(mxlo, fmaxf(s1[n][0], s1[n][1]));
                mxhi = fmaxf(mxhi, fmaxf(s1[n][2], s1[n][3]));
            }
            mxlo = fmaxf(mxlo, __shfl_xor_sync(0xffffffffu, mxlo, 1));
            mxlo = fmaxf(mxlo, __shfl_xor_sync(0xffffffffu, mxlo, 2));
            mxhi = fmaxf(mxhi, __shfl_xor_sync(0xffffffffu, mxhi, 1));
            mxhi = fmaxf(mxhi, __shfl_xor_sync(0xffffffffu, mxhi, 2));
            float mnlo = fmaxf(m1lo, mxlo), mnhi = fmaxf(m1hi, mxhi);
            float clo = __expf(m1lo - mnlo), chi = __expf(m1hi - mnhi);
            m1lo = mnlo; m1hi = mnhi;
            float sl = 0.f, shh = 0.f;
#pragma unroll
            for (int n = 0; n < 8; n++) {
                float p0 = __expf(s1[n][0] - mnlo);
                float p1 = __expf(s1[n][1] - mnlo);
                float p2 = __expf(s1[n][2] - mnhi);
                float p3 = __expf(s1[n][3] - mnhi);
                sl += p0 + p1; shh += p2 + p3;
                p1h[n][0] = pack_h2(__float2half_rn(p0), __float2half_rn(p1));
                p1h[n][1] = pack_h2(__float2half_rn(p2), __float2half_rn(p3));
            }
            sl  += __shfl_xor_sync(0xffffffffu, sl, 1);
            sl  += __shfl_xor_sync(0xffffffffu, sl, 2);
            shh += __shfl_xor_sync(0xffffffffu, shh, 1);
            shh += __shfl_xor_sync(0xffffffffu, shh, 2);
            l1lo = l1lo * clo + sl; l1hi = l1hi * chi + shh;
#pragma unroll
            for (int d = 0; d < 8; d++) {
                o1[d][0] *= clo; o1[d][1] *= clo;
                o1[d][2] *= chi; o1[d][3] *= chi;
            }
        }
        {
            float mxlo = -1e30f, mxhi = -1e30f;
#pragma unroll
            for (int n = 0; n < 8; n++) {
                mxlo = fmaxf(mxlo, fmaxf(s2[n][0], s2[n][1]));
                mxhi = fmaxf(mxhi, fmaxf(s2[n][2], s2[n][3]));
            }
            mxlo = fmaxf(mxlo, __shfl_xor_sync(0xffffffffu, mxlo, 1));
            mxlo = fmaxf(mxlo, __shfl_xor_sync(0xffffffffu, mxlo, 2));
            mxhi = fmaxf(mxhi, __shfl_xor_sync(0xffffffffu, mxhi, 1));
            mxhi = fmaxf(mxhi, __shfl_xor_sync(0xffffffffu, mxhi, 2));
            float mnlo = fmaxf(m2lo, mxlo), mnhi = fmaxf(m2hi, mxhi);
            float clo = __expf(m2lo - mnlo), chi = __expf(m2hi - mnhi);
            m2lo = mnlo; m2hi = mnhi;
            float sl = 0.f, shh = 0.f;
#pragma unroll
            for (int n = 0; n < 8; n++) {
                float p0 = __expf(s2[n][0] - mnlo);
                float p1 = __expf(s2[n][1] - mnlo);
                float p2 = __expf(s2[n][2] - mnhi);
                float p3 = __expf(s2[n][3] - mnhi);
                sl += p0 + p1; shh += p2 + p3;
                p2h[n][0] = pack_h2(__float2half_rn(p0), __float2half_rn(p1));
                p2h[n][1] = pack_h2(__float2half_rn(p2), __float2half_rn(p3));
            }
            sl  += __shfl_xor_sync(0xffffffffu, sl, 1);
            sl  += __shfl_xor_sync(0xffffffffu, sl, 2);
            shh += __shfl_xor_sync(0xffffffffu, shh, 1);
            shh += __shfl_xor_sync(0xffffffffu, shh, 2);
            l2lo = l2lo * clo + sl; l2hi = l2hi * chi + shh;
#pragma unroll
            for (int d = 0; d < 8; d++) {
                o2[d][0] *= clo; o2[d][1] *= clo;
                o2[d][2] *= chi; o2[d][3] *= chi;
            }
        }

        // ---- O += P V (V row-major [j][d], ldsm.trans) ----
        const uint32_t vb = kvb + (uint32_t)(64 * AQS) * 2u;
#pragma unroll
        for (int ks = 0; ks < 4; ks++) {
            uint32_t a1f[4] = { p1h[2*ks][0], p1h[2*ks][1], p1h[2*ks+1][0], p1h[2*ks+1][1] };
            uint32_t a2f[4] = { p2h[2*ks][0], p2h[2*ks][1], p2h[2*ks+1][0], p2h[2*ks+1][1] };
            const uint32_t jrow = (uint32_t)(ks * 16 * AQS) * 2u;
#pragma unroll
            for (int dt2 = 0; dt2 < 4; dt2++) {
                uint32_t ra = sb + vb + v_base + jrow + (uint32_t)(dt2 * 16) * 2u;
                uint32_t vh[2][2];
                ldsm_x4_t(ra, vh[0][0], vh[0][1], vh[1][0], vh[1][1]);
#pragma unroll
                for (int q = 0; q < 2; q++) {
                    int dt = dt2 * 2 + q;
                    mma_f16(o1[dt], a1f, vh[q][0], vh[q][1]);
                    mma_f16(o2[dt], a2f, vh[q][0], vh[q][1]);
                }
            }
        }

        if (kt < 15) __syncthreads();   // protect buffer overwrite by next issue
    }

    // ---- epilogue: out = O1/l1 + O2/l2 (fp16) ----
    const float i1lo = 1.f / l1lo, i1hi = 1.f / l1hi;
    const float i2lo = 1.f / l2lo, i2hi = 1.f / l2hi;
    __half* obase = outp + (size_t)b * SEQ * C_DIM;
    const int r0 = q0 + wm + (lane >> 2);
    const int cb = hoff + (lane & 3) * 2;
#pragma unroll
    for (int dt = 0; dt < 8; dt++) {
        int col = cb + dt * 8;
        float v0 = o1[dt][0] * i1lo + o2[dt][0] * i2lo;
        float v1 = o1[dt][1] * i1lo + o2[dt][1] * i2lo;
        float v2 = o1[dt][2] * i1hi + o2[dt][2] * i2hi;
        float v3 = o1[dt][3] * i1hi + o2[dt][3] * i2hi;
        *(uint32_t*)(obase + (size_t)r0 * C_DIM + col) =
            pack_h2(__float2half_rn(v0), __float2half_rn(v1));
        *(uint32_t*)(obase + (size_t)(r0 + 8) * C_DIM + col) =
            pack_h2(__float2half_rn(v2), __float2half_rn(v3));
    }
}

// ============================================================
extern "C" void kernel_launch(void* const* d_in, const int* in_sizes, int n_in,
                              void* d_out, int out_size)
{
    const float* x      = (const float*)d_in[0];
    const float* y      = (const float*)d_in[1];
    const float* w_qkv  = (const float*)d_in[2];
    const float* w_proj = (const float*)d_in[3];
    const float* b_proj = (const float*)d_in[4];
    float* out = (float*)d_out;

    __half *xh, *yh, *wqh, *wph, *qxh, *qyh, *axh, *ayh;
    cudaGetSymbolAddress((void**)&xh,  g_x_h);
    cudaGetSymbolAddress((void**)&yh,  g_y_h);
    cudaGetSymbolAddress((void**)&wqh, g_wqkv_h);
    cudaGetSymbolAddress((void**)&wph, g_wproj_h);
    cudaGetSymbolAddress((void**)&qxh, g_qkvx_h);
    cudaGetSymbolAddress((void**)&qyh, g_qkvy_h);
    cudaGetSymbolAddress((void**)&axh, g_attx_h);
    cudaGetSymbolAddress((void**)&ayh, g_atty_h);

    cudaFuncSetAttribute(gemm_mma,
                         cudaFuncAttributeMaxDynamicSharedMemorySize, GEMM_SMEM);
    cudaFuncSetAttribute(attention_mma,
                         cudaFuncAttributeMaxDynamicSharedMemorySize, ATT_SMEM);

    // 0) fp32 -> fp16 converts
    cvt_kernel<<<(M_ROWS*C_DIM/4 + 255)/256, 256>>>(x, xh, M_ROWS*C_DIM/4);
    cvt_kernel<<<(M_ROWS*C_DIM/4 + 255)/256, 256>>>(y, yh, M_ROWS*C_DIM/4);
    cvt_kernel<<<(QKV_DIM*C_DIM/4 + 255)/256, 256>>>(w_qkv, wqh, QKV_DIM*C_DIM/4);
    cvt_kernel<<<(C_DIM*C_DIM/4 + 255)/256, 256>>>(w_proj, wph, C_DIM*C_DIM/4);

    // 1) QKV projections, fp16 out; y-branch skips unused vy (n >= 2304)
    dim3 g1(QKV_DIM / 256, M_ROWS / 128, 2);
    gemm_mma<<<g1, 256, GEMM_SMEM>>>(xh, yh, wqh, nullptr,
                                     nullptr, nullptr, qxh, qyh,
                                     M_ROWS, QKV_DIM, C_DIM, 2304);

    // 2) fused dual-softmax attention (pure fp16, cp.async pipeline)
    attention_mma<<<dim3(SEQ / 128, HEADS * 2, BATCH), 256, ATT_SMEM>>>();

    // 3) output projections + bias, fp32 out
    dim3 g2(C_DIM / 256, M_ROWS / 128, 2);
    gemm_mma<<<g2, 256, GEMM_SMEM>>>(axh, ayh, wph, b_proj,
                                     out, out + (size_t)M_ROWS * C_DIM,
                                     nullptr, nullptr,
                                     M_ROWS, C_DIM, C_DIM, C_DIM);
}

// round 14
// speedup vs baseline: 2.7192x; 1.1605x over previous
#include <cuda_runtime.h>
#include <cuda_fp16.h>
#include <cstdint>

#define C_DIM   768
#define QKV_DIM 3072
#define BATCH   4
#define SEQ     1024
#define HEADS   12
#define HD      64
#define M_ROWS  (BATCH*SEQ)   // 4096

// -------- scratch (allocation-free: device globals, all fp16) --------
__device__ __half g_x_h[M_ROWS*C_DIM];
__device__ __half g_y_h[M_ROWS*C_DIM];
__device__ __half g_wqkv_h[QKV_DIM*C_DIM];
__device__ __half g_wproj_h[C_DIM*C_DIM];
__device__ __half g_qkvx_h[M_ROWS*QKV_DIM];
__device__ __half g_qkvy_h[M_ROWS*QKV_DIM];
__device__ __half g_attx_h[M_ROWS*C_DIM];
__device__ __half g_atty_h[M_ROWS*C_DIM];

// ============================================================
// helpers
// ============================================================
__device__ __forceinline__ uint32_t smem_u32(const void* p) {
    uint32_t a;
    asm("{ .reg .u64 t; cvta.to.shared.u64 t, %1; cvt.u32.u64 %0, t; }"
        : "=r"(a) : "l"(p));
    return a;
}

__device__ __forceinline__ void ldsm_x4(uint32_t addr, uint32_t& r0, uint32_t& r1,
                                        uint32_t& r2, uint32_t& r3) {
    asm volatile("ldmatrix.sync.aligned.m8n8.x4.shared.b16 {%0,%1,%2,%3}, [%4];"
                 : "=r"(r0), "=r"(r1), "=r"(r2), "=r"(r3) : "r"(addr));
}

__device__ __forceinline__ void ldsm_x4_t(uint32_t addr, uint32_t& r0, uint32_t& r1,
                                          uint32_t& r2, uint32_t& r3) {
    asm volatile("ldmatrix.sync.aligned.m8n8.x4.trans.shared.b16 {%0,%1,%2,%3}, [%4];"
                 : "=r"(r0), "=r"(r1), "=r"(r2), "=r"(r3) : "r"(addr));
}

__device__ __forceinline__ void mma_f16(float* c, const uint32_t* a,
                                        uint32_t b0, uint32_t b1) {
    asm volatile(
        "mma.sync.aligned.m16n8k16.row.col.f32.f16.f16.f32 "
        "{%0,%1,%2,%3}, {%4,%5,%6,%7}, {%8,%9}, {%0,%1,%2,%3};"
        : "+f"(c[0]), "+f"(c[1]), "+f"(c[2]), "+f"(c[3])
        : "r"(a[0]), "r"(a[1]), "r"(a[2]), "r"(a[3]), "r"(b0), "r"(b1));
}

__device__ __forceinline__ void cp_async16(uint32_t saddr, const void* gptr) {
    asm volatile("cp.async.cg.shared.global [%0], [%1], 16;"
                 :: "r"(saddr), "l"(gptr));
}
__device__ __forceinline__ void cp_commit() {
    asm volatile("cp.async.commit_group;" ::: "memory");
}
__device__ __forceinline__ void cp_wait0() { asm volatile("cp.async.wait_group 0;" ::: "memory"); }
__device__ __forceinline__ void cp_wait1() { asm volatile("cp.async.wait_group 1;" ::: "memory"); }
__device__ __forceinline__ void cp_wait2() { asm volatile("cp.async.wait_group 2;" ::: "memory"); }

__device__ __forceinline__ uint32_t pack_h2(__half a, __half b) {
    return ((uint32_t)__half_as_ushort(b) << 16) | (uint32_t)__half_as_ushort(a);
}

// fp32 float4 -> fp16 x4
__device__ __forceinline__ uint2 hi4h(float4 v) {
    return make_uint2(pack_h2(__float2half_rn(v.x), __float2half_rn(v.y)),
                      pack_h2(__float2half_rn(v.z), __float2half_rn(v.w)));
}

// ============================================================
// fused fp32 -> fp16 convert kernel (4 arrays, one launch)
// ============================================================
__global__ __launch_bounds__(256) void cvt4_kernel(
    const float* __restrict__ s0, __half* __restrict__ d0, int n0,
    const float* __restrict__ s1, __half* __restrict__ d1, int n1,
    const float* __restrict__ s2, __half* __restrict__ d2, int n2,
    const float* __restrict__ s3, __half* __restrict__ d3, int n3)
{
    int i = blockIdx.x * 256 + threadIdx.x;
    const float* s; __half* d;
    if (i < n0)                { s = s0; d = d0; }
    else if ((i -= n0) < n1)   { s = s1; d = d1; }
    else if ((i -= n1) < n2)   { s = s2; d = d2; }
    else if ((i -= n2) < n3)   { s = s3; d = d3; }
    else return;
    float4 v = ((const float4*)s)[i];
    ((uint2*)d)[i] = hi4h(v);
}

// ============================================================
// fp16 mma.sync GEMM (fp32 accum). 1-pass.
// CTA tile 128m x 128n, 8 warps (2m x 4n), warp tile 64x32.
// <=128 regs -> 2 CTAs/SM (occupancy experiment).
// BK=16, 4-deep cp.async ring, 1 sync/stage.
// qkv_scale: fold +-hd^-0.5 into q/qo output chunks.
// ============================================================
#define LDH2 24                        // halves per row (16 + 8 pad)
#define ACH  (128 * LDH2)              // 3072 halves per array (A or B)
#define STGH2 (2 * ACH)                // 6144 halves per stage
#define STGB  (STGH2 * 2)              // 12288 bytes per stage
#define GEMM_SMEM (4 * STGB)           // 49152 -> 2 CTAs/SM

__global__ __launch_bounds__(256, 2) void gemm_mma(
    const __half* __restrict__ A0, const __half* __restrict__ A1,
    const __half* __restrict__ B,
    const float* __restrict__ bias,
    float* __restrict__ Cf0, float* __restrict__ Cf1,
    __half* __restrict__ Ch0, __half* __restrict__ Ch1,
    int M, int N, int K, int n_lim1, int qkv_scale)
{
    extern __shared__ __align__(16) __half sh[];
    const int tid  = threadIdx.x;
    const int wid  = tid >> 5;
    const int lane = tid & 31;
    const int m0 = blockIdx.y * 128, n0 = blockIdx.x * 128;
    if (blockIdx.z && n0 >= n_lim1) return;   // vy skip for y-QKV
    const int wm = (wid & 1) * 64;
    const int wn = (wid >> 1) * 32;
    const int S  = K / 16;

    const __half* A = blockIdx.z ? A1 : A0;

    const uint32_t sbase = smem_u32(sh);

    auto issue_stage = [&](int s, int buf) {
        const int kb = s * 16;
        const uint32_t so = sbase + (uint32_t)buf * STGB;
#pragma unroll
        for (int j = 0; j < 2; j++) {
            int cid = tid + j * 256;             // 0..511
            int row = (cid >> 1) & 127;
            int c8  = (cid & 1) << 3;
            const __half* src = j ? (B + (size_t)(n0 + row) * K + kb + c8)
                                  : (A + (size_t)(m0 + row) * K + kb + c8);
            cp_async16(so + (uint32_t)(j * ACH + row * LDH2 + c8) * 2u, src);
        }
    };

    float acc[4][4][4];
#pragma unroll
    for (int i = 0; i < 4; i++)
#pragma unroll
        for (int j = 0; j < 4; j++)
#pragma unroll
            for (int r = 0; r < 4; r++) acc[i][j][r] = 0.f;

    const int a_off = (wm + (lane & 15)) * LDH2 + ((lane >> 4) << 3);
    const int b_off = (wn + ((lane >> 4) << 3) + (lane & 7)) * LDH2 + (((lane >> 3) & 1) << 3);

    issue_stage(0, 0); cp_commit();
    issue_stage(1, 1); cp_commit();
    issue_stage(2, 2); cp_commit();

    for (int s = 0; s < S; s++) {
        if (s + 2 < S)      cp_wait2();
        else if (s + 1 < S) cp_wait1();
        else                cp_wait0();
        __syncthreads();
        if (s + 3 < S) { issue_stage(s + 3, (s + 3) & 3); cp_commit(); }

        const uint32_t stg = sbase + (uint32_t)((s & 3) * STGB);

        uint32_t ah[4][4], bh[4][2];
#pragma unroll
        for (int mt = 0; mt < 4; mt++)
            ldsm_x4(stg + (uint32_t)(a_off + mt * 16 * LDH2) * 2u,
                    ah[mt][0], ah[mt][1], ah[mt][2], ah[mt][3]);
#pragma unroll
        for (int p = 0; p < 2; p++)
            ldsm_x4(stg + (uint32_t)(ACH + b_off + p * 16 * LDH2) * 2u,
                    bh[p*2][0], bh[p*2][1], bh[p*2+1][0], bh[p*2+1][1]);

#pragma unroll
        for (int mt = 0; mt < 4; mt++)
#pragma unroll
            for (int nt = 0; nt < 4; nt++)
                mma_f16(acc[mt][nt], ah[mt], bh[nt][0], bh[nt][1]);
    }

    // ---- epilogue ----
    if (Cf0) {
        float* C = blockIdx.z ? Cf1 : Cf0;
#pragma unroll
        for (int mt = 0; mt < 4; mt++) {
            int row0 = m0 + wm + mt * 16 + (lane >> 2);
#pragma unroll
            for (int nt = 0; nt < 4; nt++) {
                int col = n0 + wn + nt * 8 + (lane & 3) * 2;
                float b0 = 0.f, b1 = 0.f;
                if (bias) { b0 = __ldg(bias + col); b1 = __ldg(bias + col + 1); }
                float2 v0 = make_float2(acc[mt][nt][0] + b0, acc[mt][nt][1] + b1);
                float2 v1 = make_float2(acc[mt][nt][2] + b0, acc[mt][nt][3] + b1);
                *(float2*)(C + (size_t)row0 * N + col)       = v0;
                *(float2*)(C + (size_t)(row0 + 8) * N + col) = v1;
            }
        }
    } else {
        // fold attention scale into q/qo chunks (tile-uniform: 128 | 768)
        float sc = 1.f;
        if (qkv_scale) sc = (n0 < 768) ? -0.125f : (n0 < 1536 ? 0.125f : 1.f);
        __half* C = blockIdx.z ? Ch1 : Ch0;
#pragma unroll
        for (int mt = 0; mt < 4; mt++) {
            int row0 = m0 + wm + mt * 16 + (lane >> 2);
#pragma unroll
            for (int nt = 0; nt < 4; nt++) {
                int col = n0 + wn + nt * 8 + (lane & 3) * 2;
                *(uint32_t*)(C + (size_t)row0 * N + col) =
                    pack_h2(__float2half_rn(acc[mt][nt][0] * sc),
                            __float2half_rn(acc[mt][nt][1] * sc));
                *(uint32_t*)(C + (size_t)(row0 + 8) * N + col) =
                    pack_h2(__float2half_rn(acc[mt][nt][2] * sc),
                            __float2half_rn(acc[mt][nt][3] * sc));
            }
        }
    }
}

// ============================================================
// Dual-softmax flash attention, pure fp16 operands (fp32 accum).
// Q pre-scaled (+-hd^-0.5) by the QKV epilogue.
// Q/K/V via cp.async; V row-major [j][d], fragments via ldsm.trans.
// ATT_SMEM padded above 116736 B to force 1 CTA/SM (R9 lesson).
// ============================================================
#define AQS 72
#define OQ1 0
#define OQ2 (128*AQS)
#define OKV (2*128*AQS)
#define KVB (2*64*AQS)                  // per buffer: K, V
#define ATT_SMEM 117760                 // padded: > 233472/2 -> 1 CTA/SM

__global__ __launch_bounds__(256, 1) void attention_mma()
{
    extern __shared__ __align__(16) __half sh[];
    const uint32_t sb = smem_u32(sh);
    const int tid  = threadIdx.x;
    const int wid  = tid >> 5;
    const int lane = tid & 31;
    const int wm   = wid * 16;

    const int b    = blockIdx.z;
    const int h    = blockIdx.y >> 1;
    const int pair = blockIdx.y & 1;
    const int q0   = blockIdx.x * 128;
    const int hoff = h * HD;

    const __half* bx = g_qkvx_h + (size_t)b * SEQ * QKV_DIM;
    const __half* by = g_qkvy_h + (size_t)b * SEQ * QKV_DIM;

    const __half *Q1src, *Q2src, *Ksrc;
    __half* outp;
    if (pair == 0) { Q1src = bx + C_DIM; Q2src = by;  Ksrc = bx + 2 * C_DIM; outp = g_attx_h; }
    else           { Q1src = by + C_DIM; Q2src = bx;  Ksrc = by + 2 * C_DIM; outp = g_atty_h; }
    const __half* Vsrc = bx + 3 * C_DIM;   // vy = vx in the reference
    Q1src += hoff; Q2src += hoff; Ksrc += hoff; Vsrc += hoff;

    // ---- issue Q tiles (one-time, 8 cp.async/thread) ----
    {
        const __half* qs[2] = { Q1src, Q2src };
#pragma unroll
        for (int a = 0; a < 2; a++)
#pragma unroll
            for (int j = 0; j < 4; j++) {
                int cid = tid + j * 256;         // 0..1023
                int row = cid >> 3;              // 0..127
                int c8  = (cid & 7) << 3;        // 0..56
                cp_async16(sb + (uint32_t)(a * 128 * AQS + row * AQS + c8) * 2u,
                           qs[a] + (size_t)(q0 + row) * QKV_DIM + c8);
            }
    }

    // KV tile: 64 rows x 64 halves per tensor -> 512 slots -> 2/thread/tensor
    auto issue_kv = [&](int kt, int buf) {
        const int j0 = kt * 64;
        const int nb = OKV + buf * KVB;
#pragma unroll
        for (int j = 0; j < 2; j++) {
            int cid = tid + j * 256;             // 0..511
            int row = cid >> 3;                  // 0..63
            int c8  = (cid & 7) << 3;            // 0..56
            cp_async16(sb + (uint32_t)(nb + row * AQS + c8) * 2u,
                       Ksrc + (size_t)(j0 + row) * QKV_DIM + c8);
            cp_async16(sb + (uint32_t)(nb + 64 * AQS + row * AQS + c8) * 2u,
                       Vsrc + (size_t)(j0 + row) * QKV_DIM + c8);
        }
    };

    issue_kv(0, 0);
    cp_commit();   // group 0: Q + KV tile 0

    float o1[8][4], o2[8][4];
#pragma unroll
    for (int d = 0; d < 8; d++)
#pragma unroll
        for (int r = 0; r < 4; r++) { o1[d][r] = 0.f; o2[d][r] = 0.f; }
    float m1lo = -1e30f, m1hi = -1e30f, l1lo = 0.f, l1hi = 0.f;
    float m2lo = -1e30f, m2hi = -1e30f, l2lo = 0.f, l2hi = 0.f;

    const uint32_t a_base = (uint32_t)((wm + (lane & 15)) * AQS + ((lane >> 4) << 3)) * 2u;
    const uint32_t b_base = (uint32_t)((((lane >> 4) << 3) + (lane & 7)) * AQS
                                       + (((lane >> 3) & 1) << 3)) * 2u;
    const uint32_t v_base = (uint32_t)(((((lane >> 3) & 1) << 3) + (lane & 7)) * AQS
                                       + ((lane >> 4) << 3)) * 2u;

    for (int kt = 0; kt < 16; kt++) {
        const uint32_t kvb = (uint32_t)(OKV + (kt & 1) * KVB) * 2u;

        if (kt < 15) { issue_kv(kt + 1, (kt + 1) & 1); cp_commit(); cp_wait1(); }
        else         { cp_wait0(); }
        __syncthreads();

        // ---- S = Q K^T (fp16 x fp16 -> fp32; scale pre-folded) ----
        float s1[8][4], s2[8][4];
#pragma unroll
        for (int n = 0; n < 8; n++)
#pragma unroll
            for (int r = 0; r < 4; r++) { s1[n][r] = 0.f; s2[n][r] = 0.f; }

#pragma unroll
        for (int ks = 0; ks < 4; ks++) {
            const uint32_t kofs = (uint32_t)(ks * 16) * 2u;
            uint32_t a1h[4], a2h[4];
            ldsm_x4(sb + (uint32_t)(OQ1*2) + a_base + kofs, a1h[0], a1h[1], a1h[2], a1h[3]);
            ldsm_x4(sb + (uint32_t)(OQ2*2) + a_base + kofs, a2h[0], a2h[1], a2h[2], a2h[3]);
#pragma unroll
            for (int jt = 0; jt < 4; jt++) {
                uint32_t rb = sb + kvb + b_base + (uint32_t)(jt * 16 * AQS) * 2u + kofs;
                uint32_t bh[2][2];
                ldsm_x4(rb, bh[0][0], bh[0][1], bh[1][0], bh[1][1]);
#pragma unroll
                for (int q = 0; q < 2; q++) {
                    int nt = jt * 2 + q;
                    mma_f16(s1[nt], a1h, bh[q][0], bh[q][1]);
                    mma_f16(s2[nt], a2h, bh[q][0], bh[q][1]);
                }
            }
        }

        // ---- online softmax (per stream), P as fp16 ----
        uint32_t p1h[8][2], p2h[8][2];
        {
            float mxlo = -1e30f, mxhi = -1e30f;
#pragma unroll
            for (int n = 0; n < 8; n++) {
                mxlo = fmaxf(mxlo, fmaxf(s1[n][0], s1[n][1]));
                mxhi = fmaxf(mxhi, fmaxf(s1[n][2], s1[n][3]));
            }
            mxlo = fmaxf(mxlo, __shfl_xor_sync(0xffffffffu, mxlo, 1));
            mxlo = fmaxf(mxlo, __shfl_xor_sync(0xffffffffu, mxlo, 2));
            mxhi = fmaxf(mxhi, __shfl_xor_sync(0xffffffffu, mxhi, 1));
            mxhi = fmaxf(mxhi, __shfl_xor_sync(0xffffffffu, mxhi, 2));
            float mnlo = fmaxf(m1lo, mxlo), mnhi = fmaxf(m1hi, mxhi);
            float clo = __expf(m1lo - mnlo), chi = __expf(m1hi - mnhi);
            m1lo = mnlo; m1hi = mnhi;
            float sl = 0.f, shh = 0.f;
#pragma unroll
            for (int n = 0; n < 8; n++) {
                float p0 = __expf(s1[n][0] - mnlo);
                float p1 = __expf(s1[n][1] - mnlo);
                float p2 = __expf(s1[n][2] - mnhi);
                float p3 = __expf(s1[n][3] - mnhi);
                sl += p0 + p1; shh += p2 + p3;
                p1h[n][0] = pack_h2(__float2half_rn(p0), __float2half_rn(p1));
                p1h[n][1] = pack_h2(__float2half_rn(p2), __float2half_rn(p3));
            }
            sl  += __shfl_xor_sync(0xffffffffu, sl, 1);
            sl  += __shfl_xor_sync(0xffffffffu, sl, 2);
            shh += __shfl_xor_sync(0xffffffffu, shh, 1);
            shh += __shfl_xor_sync(0xffffffffu, shh, 2);
            l1lo = l1lo * clo + sl; l1hi = l1hi * chi + shh;
#pragma unroll
            for (int d = 0; d < 8; d++) {
                o1[d][0] *= clo; o1[d][1] *= clo;
                o1[d][2] *= chi; o1[d][3] *= chi;
            }
        }
        {
            float mxlo = -1e30f, mxhi = -1e30f;
#pragma unroll
            for (int n = 0; n < 8; n++) {
                mxlo = fmaxf(mxlo, fmaxf(s2[n][0], s2[n][1]));
                mxhi = fmaxf(mxhi, fmaxf(s2[n][2], s2[n][3]));
            }
            mxlo = fmaxf(mxlo, __shfl_xor_sync(0xffffffffu, mxlo, 1));
            mxlo = fmaxf(mxlo, __shfl_xor_sync(0xffffffffu, mxlo, 2));
            mxhi = fmaxf(mxhi, __shfl_xor_sync(0xffffffffu, mxhi, 1));
            mxhi = fmaxf(mxhi, __shfl_xor_sync(0xffffffffu, mxhi, 2));
            float mnlo = fmaxf(m2lo, mxlo), mnhi = fmaxf(m2hi, mxhi);
            float clo = __expf(m2lo - mnlo), chi = __expf(m2hi - mnhi);
            m2lo = mnlo; m2hi = mnhi;
            float sl = 0.f, shh = 0.f;
#pragma unroll
            for (int n = 0; n < 8; n++) {
                float p0 = __expf(s2[n][0] - mnlo);
                float p1 = __expf(s2[n][1] - mnlo);
                float p2 = __expf(s2[n][2] - mnhi);
                float p3 = __expf(s2[n][3] - mnhi);
                sl += p0 + p1; shh += p2 + p3;
                p2h[n][0] = pack_h2(__float2half_rn(p0), __float2half_rn(p1));
                p2h[n][1] = pack_h2(__float2half_rn(p2), __float2half_rn(p3));
            }
            sl  += __shfl_xor_sync(0xffffffffu, sl, 1);
            sl  += __shfl_xor_sync(0xffffffffu, sl, 2);
            shh += __shfl_xor_sync(0xffffffffu, shh, 1);
            shh += __shfl_xor_sync(0xffffffffu, shh, 2);
            l2lo = l2lo * clo + sl; l2hi = l2hi * chi + shh;
#pragma unroll
            for (int d = 0; d < 8; d++) {
                o2[d][0] *= clo; o2[d][1] *= clo;
                o2[d][2] *= chi; o2[d][3] *= chi;
            }
        }

        // ---- O += P V (V row-major [j][d], ldsm.trans) ----
        const uint32_t vb = kvb + (uint32_t)(64 * AQS) * 2u;
#pragma unroll
        for (int ks = 0; ks < 4; ks++) {
            uint32_t a1f[4] = { p1h[2*ks][0], p1h[2*ks][1], p1h[2*ks+1][0], p1h[2*ks+1][1] };
            uint32_t a2f[4] = { p2h[2*ks][0], p2h[2*ks][1], p2h[2*ks+1][0], p2h[2*ks+1][1] };
            const uint32_t jrow = (uint32_t)(ks * 16 * AQS) * 2u;
#pragma unroll
            for (int dt2 = 0; dt2 < 4; dt2++) {
                uint32_t ra = sb + vb + v_base + jrow + (uint32_t)(dt2 * 16) * 2u;
                uint32_t vh[2][2];
                ldsm_x4_t(ra, vh[0][0], vh[0][1], vh[1][0], vh[1][1]);
#pragma unroll
                for (int q = 0; q < 2; q++) {
                    int dt = dt2 * 2 + q;
                    mma_f16(o1[dt], a1f, vh[q][0], vh[q][1]);
                    mma_f16(o2[dt], a2f, vh[q][0], vh[q][1]);
                }
            }
        }

        if (kt < 15) __syncthreads();   // protect buffer overwrite by next issue
    }

    // ---- epilogue: out = O1/l1 + O2/l2 (fp16) ----
    const float i1lo = 1.f / l1lo, i1hi = 1.f / l1hi;
    const float i2lo = 1.f / l2lo, i2hi = 1.f / l2hi;
    __half* obase = outp + (size_t)b * SEQ * C_DIM;
    const int r0 = q0 + wm + (lane >> 2);
    const int cb = hoff + (lane & 3) * 2;
#pragma unroll
    for (int dt = 0; dt < 8; dt++) {
        int col = cb + dt * 8;
        float v0 = o1[dt][0] * i1lo + o2[dt][0] * i2lo;
        float v1 = o1[dt][1] * i1lo + o2[dt][1] * i2lo;
        float v2 = o1[dt][2] * i1hi + o2[dt][2] * i2hi;
        float v3 = o1[dt][3] * i1hi + o2[dt][3] * i2hi;
        *(uint32_t*)(obase + (size_t)r0 * C_DIM + col) =
            pack_h2(__float2half_rn(v0), __float2half_rn(v1));
        *(uint32_t*)(obase + (size_t)(r0 + 8) * C_DIM + col) =
            pack_h2(__float2half_rn(v2), __float2half_rn(v3));
    }
}

// ============================================================
extern "C" void kernel_launch(void* const* d_in, const int* in_sizes, int n_in,
                              void* d_out, int out_size)
{
    const float* x      = (const float*)d_in[0];
    const float* y      = (const float*)d_in[1];
    const float* w_qkv  = (const float*)d_in[2];
    const float* w_proj = (const float*)d_in[3];
    const float* b_proj = (const float*)d_in[4];
    float* out = (float*)d_out;

    __half *xh, *yh, *wqh, *wph, *qxh, *qyh, *axh, *ayh;
    cudaGetSymbolAddress((void**)&xh,  g_x_h);
    cudaGetSymbolAddress((void**)&yh,  g_y_h);
    cudaGetSymbolAddress((void**)&wqh, g_wqkv_h);
    cudaGetSymbolAddress((void**)&wph, g_wproj_h);
    cudaGetSymbolAddress((void**)&qxh, g_qkvx_h);
    cudaGetSymbolAddress((void**)&qyh, g_qkvy_h);
    cudaGetSymbolAddress((void**)&axh, g_attx_h);
    cudaGetSymbolAddress((void**)&ayh, g_atty_h);

    cudaFuncSetAttribute(gemm_mma,
                         cudaFuncAttributeMaxDynamicSharedMemorySize, GEMM_SMEM);
    cudaFuncSetAttribute(attention_mma,
                         cudaFuncAttributeMaxDynamicSharedMemorySize, ATT_SMEM);

    // 0) fp32 -> fp16 converts (single fused launch)
    const int nx = M_ROWS*C_DIM/4, nw = QKV_DIM*C_DIM/4, np = C_DIM*C_DIM/4;
    cvt4_kernel<<<(nx + nx + nw + np + 255)/256, 256>>>(
        x, xh, nx, y, yh, nx, w_qkv, wqh, nw, w_proj, wph, np);

    // 1) QKV projections, fp16 out, scale folded; y skips unused vy
    dim3 g1(QKV_DIM / 128, M_ROWS / 128, 2);
    gemm_mma<<<g1, 256, GEMM_SMEM>>>(xh, yh, wqh, nullptr,
                                     nullptr, nullptr, qxh, qyh,
                                     M_ROWS, QKV_DIM, C_DIM, 2304, 1);

    // 2) fused dual-softmax attention (pure fp16, scale pre-folded)
    attention_mma<<<dim3(SEQ / 128, HEADS * 2, BATCH), 256, ATT_SMEM>>>();

    // 3) output projections + bias, fp32 out
    dim3 g2(C_DIM / 128, M_ROWS / 128, 2);
    gemm_mma<<<g2, 256, GEMM_SMEM>>>(axh, ayh, wph, b_proj,
                                     out, out + (size_t)M_ROWS * C_DIM,
                                     nullptr, nullptr,
                                     M_ROWS, C_DIM, C_DIM, C_DIM, 0);
}

// round 15
// speedup vs baseline: 2.8824x; 1.0600x over previous
#include <cuda_runtime.h>
#include <cuda_fp16.h>
#include <cstdint>

#define C_DIM   768
#define QKV_DIM 3072
#define BATCH   4
#define SEQ     1024
#define HEADS   12
#define HD      64
#define M_ROWS  (BATCH*SEQ)   // 4096

// -------- scratch (allocation-free: device globals, all fp16) --------
__device__ __half g_x_h[M_ROWS*C_DIM];
__device__ __half g_y_h[M_ROWS*C_DIM];
__device__ __half g_wqkv_h[QKV_DIM*C_DIM];
__device__ __half g_wproj_h[C_DIM*C_DIM];
__device__ __half g_qkvx_h[M_ROWS*QKV_DIM];
__device__ __half g_qkvy_h[M_ROWS*QKV_DIM];
__device__ __half g_attx_h[M_ROWS*C_DIM];
__device__ __half g_atty_h[M_ROWS*C_DIM];

// ============================================================
// helpers
// ============================================================
__device__ __forceinline__ uint32_t smem_u32(const void* p) {
    uint32_t a;
    asm("{ .reg .u64 t; cvta.to.shared.u64 t, %1; cvt.u32.u64 %0, t; }"
        : "=r"(a) : "l"(p));
    return a;
}

__device__ __forceinline__ void ldsm_x4(uint32_t addr, uint32_t& r0, uint32_t& r1,
                                        uint32_t& r2, uint32_t& r3) {
    asm volatile("ldmatrix.sync.aligned.m8n8.x4.shared.b16 {%0,%1,%2,%3}, [%4];"
                 : "=r"(r0), "=r"(r1), "=r"(r2), "=r"(r3) : "r"(addr));
}

__device__ __forceinline__ void ldsm_x4_t(uint32_t addr, uint32_t& r0, uint32_t& r1,
                                          uint32_t& r2, uint32_t& r3) {
    asm volatile("ldmatrix.sync.aligned.m8n8.x4.trans.shared.b16 {%0,%1,%2,%3}, [%4];"
                 : "=r"(r0), "=r"(r1), "=r"(r2), "=r"(r3) : "r"(addr));
}

__device__ __forceinline__ void mma_f16(float* c, const uint32_t* a,
                                        uint32_t b0, uint32_t b1) {
    asm volatile(
        "mma.sync.aligned.m16n8k16.row.col.f32.f16.f16.f32 "
        "{%0,%1,%2,%3}, {%4,%5,%6,%7}, {%8,%9}, {%0,%1,%2,%3};"
        : "+f"(c[0]), "+f"(c[1]), "+f"(c[2]), "+f"(c[3])
        : "r"(a[0]), "r"(a[1]), "r"(a[2]), "r"(a[3]), "r"(b0), "r"(b1));
}

__device__ __forceinline__ void cp_async16(uint32_t saddr, const void* gptr) {
    asm volatile("cp.async.cg.shared.global [%0], [%1], 16;"
                 :: "r"(saddr), "l"(gptr));
}
__device__ __forceinline__ void cp_commit() {
    asm volatile("cp.async.commit_group;" ::: "memory");
}
__device__ __forceinline__ void cp_wait0() { asm volatile("cp.async.wait_group 0;" ::: "memory"); }
__device__ __forceinline__ void cp_wait1() { asm volatile("cp.async.wait_group 1;" ::: "memory"); }
__device__ __forceinline__ void cp_wait2() { asm volatile("cp.async.wait_group 2;" ::: "memory"); }

__device__ __forceinline__ uint32_t pack_h2(__half a, __half b) {
    return ((uint32_t)__half_as_ushort(b) << 16) | (uint32_t)__half_as_ushort(a);
}

// fp32 float4 -> fp16 x4
__device__ __forceinline__ uint2 hi4h(float4 v) {
    return make_uint2(pack_h2(__float2half_rn(v.x), __float2half_rn(v.y)),
                      pack_h2(__float2half_rn(v.z), __float2half_rn(v.w)));
}

// ============================================================
// fused fp32 -> fp16 convert kernel (4 arrays, one launch, 4x ILP)
// ============================================================
__device__ __forceinline__ void cvt_one(
    int i,
    const float* __restrict__ s0, __half* __restrict__ d0, int n0,
    const float* __restrict__ s1, __half* __restrict__ d1, int n1,
    const float* __restrict__ s2, __half* __restrict__ d2, int n2,
    const float* __restrict__ s3, __half* __restrict__ d3, int n3)
{
    const float* s; __half* d;
    if (i < n0)                { s = s0; d = d0; }
    else if ((i -= n0) < n1)   { s = s1; d = d1; }
    else if ((i -= n1) < n2)   { s = s2; d = d2; }
    else if ((i -= n2) < n3)   { s = s3; d = d3; }
    else return;
    float4 v = ((const float4*)s)[i];
    ((uint2*)d)[i] = hi4h(v);
}

__global__ __launch_bounds__(256) void cvt4_kernel(
    const float* __restrict__ s0, __half* __restrict__ d0, int n0,
    const float* __restrict__ s1, __half* __restrict__ d1, int n1,
    const float* __restrict__ s2, __half* __restrict__ d2, int n2,
    const float* __restrict__ s3, __half* __restrict__ d3, int n3)
{
    int base = blockIdx.x * 1024 + threadIdx.x;
#pragma unroll
    for (int u = 0; u < 4; u++)
        cvt_one(base + u * 256, s0, d0, n0, s1, d1, n1, s2, d2, n2, s3, d3, n3);
}

// ============================================================
// fp16 mma.sync GEMM (fp32 accum). 1-pass.
// CTA tile 128m x 128n, 8 warps (2m x 4n), warp tile 64x32.
// BK=32 (32 MMAs/warp per stage), 4-deep cp.async ring, 1 sync/stage.
// <=128 regs -> 2 CTAs/SM. qkv_scale folds +-hd^-0.5 into q chunks.
// ============================================================
#define LDH3 40                        // halves per row (32 + 8 pad)
#define ACH3 (128 * LDH3)              // 5120 halves per array (A or B)
#define STGB3 (2 * ACH3 * 2)           // 20480 bytes per stage
#define GEMM_SMEM (4 * STGB3)          // 81920 -> 2 CTAs/SM

__global__ __launch_bounds__(256, 2) void gemm_mma(
    const __half* __restrict__ A0, const __half* __restrict__ A1,
    const __half* __restrict__ B,
    const float* __restrict__ bias,
    float* __restrict__ Cf0, float* __restrict__ Cf1,
    __half* __restrict__ Ch0, __half* __restrict__ Ch1,
    int M, int N, int K, int n_lim1, int qkv_scale)
{
    extern __shared__ __align__(16) __half sh[];
    const int tid  = threadIdx.x;
    const int wid  = tid >> 5;
    const int lane = tid & 31;
    const int m0 = blockIdx.y * 128, n0 = blockIdx.x * 128;
    if (blockIdx.z && n0 >= n_lim1) return;   // vy skip for y-QKV
    const int wm = (wid & 1) * 64;
    const int wn = (wid >> 1) * 32;
    const int S  = K / 32;

    const __half* A = blockIdx.z ? A1 : A0;

    const uint32_t sbase = smem_u32(sh);

    auto issue_stage = [&](int s, int buf) {
        const int kb = s * 32;
        const uint32_t so = sbase + (uint32_t)buf * STGB3;
#pragma unroll
        for (int j = 0; j < 2; j++) {
            int cid = tid + j * 256;             // 0..511
            int row = cid >> 2;                  // 0..127
            int c8  = (cid & 3) << 3;            // 0,8,16,24 halves
            cp_async16(so + (uint32_t)(row * LDH3 + c8) * 2u,
                       A + (size_t)(m0 + row) * K + kb + c8);
            cp_async16(so + (uint32_t)(ACH3 + row * LDH3 + c8) * 2u,
                       B + (size_t)(n0 + row) * K + kb + c8);
        }
    };

    float acc[4][4][4];
#pragma unroll
    for (int i = 0; i < 4; i++)
#pragma unroll
        for (int j = 0; j < 4; j++)
#pragma unroll
            for (int r = 0; r < 4; r++) acc[i][j][r] = 0.f;

    const int a_off = (wm + (lane & 15)) * LDH3 + ((lane >> 4) << 3);
    const int b_off = (wn + ((lane >> 4) << 3) + (lane & 7)) * LDH3 + (((lane >> 3) & 1) << 3);

    issue_stage(0, 0); cp_commit();
    issue_stage(1, 1); cp_commit();
    issue_stage(2, 2); cp_commit();

    for (int s = 0; s < S; s++) {
        if (s + 2 < S)      cp_wait2();
        else if (s + 1 < S) cp_wait1();
        else                cp_wait0();
        __syncthreads();
        if (s + 3 < S) { issue_stage(s + 3, (s + 3) & 3); cp_commit(); }

        const uint32_t stg = sbase + (uint32_t)((s & 3) * STGB3);

#pragma unroll
        for (int ks = 0; ks < 2; ks++) {
            const uint32_t kofs = (uint32_t)(ks * 16) * 2u;
            uint32_t ah[4][4], bh[4][2];
#pragma unroll
            for (int mt = 0; mt < 4; mt++)
                ldsm_x4(stg + kofs + (uint32_t)(a_off + mt * 16 * LDH3) * 2u,
                        ah[mt][0], ah[mt][1], ah[mt][2], ah[mt][3]);
#pragma unroll
            for (int p = 0; p < 2; p++)
                ldsm_x4(stg + kofs + (uint32_t)(ACH3 + b_off + p * 16 * LDH3) * 2u,
                        bh[p*2][0], bh[p*2][1], bh[p*2+1][0], bh[p*2+1][1]);

#pragma unroll
            for (int mt = 0; mt < 4; mt++)
#pragma unroll
                for (int nt = 0; nt < 4; nt++)
                    mma_f16(acc[mt][nt], ah[mt], bh[nt][0], bh[nt][1]);
        }
    }

    // ---- epilogue ----
    if (Cf0) {
        float* C = blockIdx.z ? Cf1 : Cf0;
#pragma unroll
        for (int mt = 0; mt < 4; mt++) {
            int row0 = m0 + wm + mt * 16 + (lane >> 2);
#pragma unroll
            for (int nt = 0; nt < 4; nt++) {
                int col = n0 + wn + nt * 8 + (lane & 3) * 2;
                float b0 = 0.f, b1 = 0.f;
                if (bias) { b0 = __ldg(bias + col); b1 = __ldg(bias + col + 1); }
                float2 v0 = make_float2(acc[mt][nt][0] + b0, acc[mt][nt][1] + b1);
                float2 v1 = make_float2(acc[mt][nt][2] + b0, acc[mt][nt][3] + b1);
                *(float2*)(C + (size_t)row0 * N + col)       = v0;
                *(float2*)(C + (size_t)(row0 + 8) * N + col) = v1;
            }
        }
    } else {
        // fold attention scale into q/qo chunks (tile-uniform: 128 | 768)
        float sc = 1.f;
        if (qkv_scale) sc = (n0 < 768) ? -0.125f : (n0 < 1536 ? 0.125f : 1.f);
        __half* C = blockIdx.z ? Ch1 : Ch0;
#pragma unroll
        for (int mt = 0; mt < 4; mt++) {
            int row0 = m0 + wm + mt * 16 + (lane >> 2);
#pragma unroll
            for (int nt = 0; nt < 4; nt++) {
                int col = n0 + wn + nt * 8 + (lane & 3) * 2;
                *(uint32_t*)(C + (size_t)row0 * N + col) =
                    pack_h2(__float2half_rn(acc[mt][nt][0] * sc),
                            __float2half_rn(acc[mt][nt][1] * sc));
                *(uint32_t*)(C + (size_t)(row0 + 8) * N + col) =
                    pack_h2(__float2half_rn(acc[mt][nt][2] * sc),
                            __float2half_rn(acc[mt][nt][3] * sc));
            }
        }
    }
}

// ============================================================
// Dual-softmax flash attention, pure fp16 operands (fp32 accum).
// Q pre-scaled (+-hd^-0.5) by the QKV epilogue.
// Q/K/V via cp.async; V row-major [j][d], fragments via ldsm.trans.
// ATT_SMEM padded above 116736 B to force 1 CTA/SM (R9 lesson).
// (measured at the 270 TF/s mma.sync wall in R14 -- unchanged)
// ============================================================
#define AQS 72
#define OQ1 0
#define OQ2 (128*AQS)
#define OKV (2*128*AQS)
#define KVB (2*64*AQS)                  // per buffer: K, V
#define ATT_SMEM 117760                 // padded: > 233472/2 -> 1 CTA/SM

__global__ __launch_bounds__(256, 1) void attention_mma()
{
    extern __shared__ __align__(16) __half sh[];
    const uint32_t sb = smem_u32(sh);
    const int tid  = threadIdx.x;
    const int wid  = tid >> 5;
    const int lane = tid & 31;
    const int wm   = wid * 16;

    const int b    = blockIdx.z;
    const int h    = blockIdx.y >> 1;
    const int pair = blockIdx.y & 1;
    const int q0   = blockIdx.x * 128;
    const int hoff = h * HD;

    const __half* bx = g_qkvx_h + (size_t)b * SEQ * QKV_DIM;
    const __half* by = g_qkvy_h + (size_t)b * SEQ * QKV_DIM;

    const __half *Q1src, *Q2src, *Ksrc;
    __half* outp;
    if (pair == 0) { Q1src = bx + C_DIM; Q2src = by;  Ksrc = bx + 2 * C_DIM; outp = g_attx_h; }
    else           { Q1src = by + C_DIM; Q2src = bx;  Ksrc = by + 2 * C_DIM; outp = g_atty_h; }
    const __half* Vsrc = bx + 3 * C_DIM;   // vy = vx in the reference
    Q1src += hoff; Q2src += hoff; Ksrc += hoff; Vsrc += hoff;

    // ---- issue Q tiles (one-time, 8 cp.async/thread) ----
    {
        const __half* qs[2] = { Q1src, Q2src };
#pragma unroll
        for (int a = 0; a < 2; a++)
#pragma unroll
            for (int j = 0; j < 4; j++) {
                int cid = tid + j * 256;         // 0..1023
                int row = cid >> 3;              // 0..127
                int c8  = (cid & 7) << 3;        // 0..56
                cp_async16(sb + (uint32_t)(a * 128 * AQS + row * AQS + c8) * 2u,
                           qs[a] + (size_t)(q0 + row) * QKV_DIM + c8);
            }
    }

    // KV tile: 64 rows x 64 halves per tensor -> 512 slots -> 2/thread/tensor
    auto issue_kv = [&](int kt, int buf) {
        const int j0 = kt * 64;
        const int nb = OKV + buf * KVB;
#pragma unroll
        for (int j = 0; j < 2; j++) {
            int cid = tid + j * 256;             // 0..511
            int row = cid >> 3;                  // 0..63
            int c8  = (cid & 7) << 3;            // 0..56
            cp_async16(sb + (uint32_t)(nb + row * AQS + c8) * 2u,
                       Ksrc + (size_t)(j0 + row) * QKV_DIM + c8);
            cp_async16(sb + (uint32_t)(nb + 64 * AQS + row * AQS + c8) * 2u,
                       Vsrc + (size_t)(j0 + row) * QKV_DIM + c8);
        }
    };

    issue_kv(0, 0);
    cp_commit();   // group 0: Q + KV tile 0

    float o1[8][4], o2[8][4];
#pragma unroll
    for (int d = 0; d < 8; d++)
#pragma unroll
        for (int r = 0; r < 4; r++) { o1[d][r] = 0.f; o2[d][r] = 0.f; }
    float m1lo = -1e30f, m1hi = -1e30f, l1lo = 0.f, l1hi = 0.f;
    float m2lo = -1e30f, m2hi = -1e30f, l2lo = 0.f, l2hi = 0.f;

    const uint32_t a_base = (uint32_t)((wm + (lane & 15)) * AQS + ((lane >> 4) << 3)) * 2u;
    const uint32_t b_base = (uint32_t)((((lane >> 4) << 3) + (lane & 7)) * AQS
                                       + (((lane >> 3) & 1) << 3)) * 2u;
    const uint32_t v_base = (uint32_t)(((((lane >> 3) & 1) << 3) + (lane & 7)) * AQS
                                       + ((lane >> 4) << 3)) * 2u;

    for (int kt = 0; kt < 16; kt++) {
        const uint32_t kvb = (uint32_t)(OKV + (kt & 1) * KVB) * 2u;

        if (kt < 15) { issue_kv(kt + 1, (kt + 1) & 1); cp_commit(); cp_wait1(); }
        else         { cp_wait0(); }
        __syncthreads();

        // ---- S = Q K^T (fp16 x fp16 -> fp32; scale pre-folded) ----
        float s1[8][4], s2[8][4];
#pragma unroll
        for (int n = 0; n < 8; n++)
#pragma unroll
            for (int r = 0; r < 4; r++) { s1[n][r] = 0.f; s2[n][r] = 0.f; }

#pragma unroll
        for (int ks = 0; ks < 4; ks++) {
            const uint32_t kofs = (uint32_t)(ks * 16) * 2u;
            uint32_t a1h[4], a2h[4];
            ldsm_x4(sb + (uint32_t)(OQ1*2) + a_base + kofs, a1h[0], a1h[1], a1h[2], a1h[3]);
            ldsm_x4(sb + (uint32_t)(OQ2*2) + a_base + kofs, a2h[0], a2h[1], a2h[2], a2h[3]);
#pragma unroll
            for (int jt = 0; jt < 4; jt++) {
                uint32_t rb = sb + kvb + b_base + (uint32_t)(jt * 16 * AQS) * 2u + kofs;
                uint32_t bh[2][2];
                ldsm_x4(rb, bh[0][0], bh[0][1], bh[1][0], bh[1][1]);
#pragma unroll
                for (int q = 0; q < 2; q++) {
                    int nt = jt * 2 + q;
                    mma_f16(s1[nt], a1h, bh[q][0], bh[q][1]);
                    mma_f16(s2[nt], a2h, bh[q][0], bh[q][1]);
                }
            }
        }

        // ---- online softmax (per stream), P as fp16 ----
        uint32_t p1h[8][2], p2h[8][2];
        {
            float mxlo = -1e30f, mxhi = -1e30f;
#pragma unroll
            for (int n = 0; n < 8; n++) {
                mxlo = fmaxf(mxlo, fmaxf(s1[n][0], s1[n][1]));
                mxhi = fmaxf(mxhi, fmaxf(s1[n][2], s1[n][3]));
            }
            mxlo = fmaxf(mxlo, __shfl_xor_sync(0xffffffffu, mxlo, 1));
            mxlo = fmaxf(mxlo, __shfl_xor_sync(0xffffffffu, mxlo, 2));
            mxhi = fmaxf(mxhi, __shfl_xor_sync(0xffffffffu, mxhi, 1));
            mxhi = fmaxf(mxhi, __shfl_xor_sync(0xffffffffu, mxhi, 2));
            float mnlo = fmaxf(m1lo, mxlo), mnhi = fmaxf(m1hi, mxhi);
            float clo = __expf(m1lo - mnlo), chi = __expf(m1hi - mnhi);
            m1lo = mnlo; m1hi = mnhi;
            float sl = 0.f, shh = 0.f;
#pragma unroll
            for (int n = 0; n < 8; n++) {
                float p0 = __expf(s1[n][0] - mnlo);
                float p1 = __expf(s1[n][1] - mnlo);
                float p2 = __expf(s1[n][2] - mnhi);
                float p3 = __expf(s1[n][3] - mnhi);
                sl += p0 + p1; shh += p2 + p3;
                p1h[n][0] = pack_h2(__float2half_rn(p0), __float2half_rn(p1));
                p1h[n][1] = pack_h2(__float2half_rn(p2), __float2half_rn(p3));
            }
            sl  += __shfl_xor_sync(0xffffffffu, sl, 1);
            sl  += __shfl_xor_sync(0xffffffffu, sl, 2);
            shh += __shfl_xor_sync(0xffffffffu, shh, 1);
            shh += __shfl_xor_sync(0xffffffffu, shh, 2);
            l1lo = l1lo * clo + sl; l1hi = l1hi * chi + shh;
#pragma unroll
            for (int d = 0; d < 8; d++) {
                o1[d][0] *= clo; o1[d][1] *= clo;
                o1[d][2] *= chi; o1[d][3] *= chi;
            }
        }
        {
            float mxlo = -1e30f, mxhi = -1e30f;
#pragma unroll
            for (int n = 0; n < 8; n++) {
                mxlo = fmaxf(mxlo, fmaxf(s2[n][0], s2[n][1]));
                mxhi = fmaxf(mxhi, fmaxf(s2[n][2], s2[n][3]));
            }
            mxlo = fmaxf(mxlo, __shfl_xor_sync(0xffffffffu, mxlo, 1));
            mxlo = fmaxf(mxlo, __shfl_xor_sync(0xffffffffu, mxlo, 2));
            mxhi = fmaxf(mxhi, __shfl_xor_sync(0xffffffffu, mxhi, 1));
            mxhi = fmaxf(mxhi, __shfl_xor_sync(0xffffffffu, mxhi, 2));
            float mnlo = fmaxf(m2lo, mxlo), mnhi = fmaxf(m2hi, mxhi);
            float clo = __expf(m2lo - mnlo), chi = __expf(m2hi - mnhi);
            m2lo = mnlo; m2hi = mnhi;
            float sl = 0.f, shh = 0.f;
#pragma unroll
            for (int n = 0; n < 8; n++) {
                float p0 = __expf(s2[n][0] - mnlo);
                float p1 = __expf(s2[n][1] - mnlo);
                float p2 = __expf(s2[n][2] - mnhi);
                float p3 = __expf(s2[n][3] - mnhi);
                sl += p0 + p1; shh += p2 + p3;
                p2h[n][0] = pack_h2(__float2half_rn(p0), __float2half_rn(p1));
                p2h[n][1] = pack_h2(__float2half_rn(p2), __float2half_rn(p3));
            }
            sl  += __shfl_xor_sync(0xffffffffu, sl, 1);
            sl  += __shfl_xor_sync(0xffffffffu, sl, 2);
            shh += __shfl_xor_sync(0xffffffffu, shh, 1);
            shh += __shfl_xor_sync(0xffffffffu, shh, 2);
            l2lo = l2lo * clo + sl; l2hi = l2hi * chi + shh;
#pragma unroll
            for (int d = 0; d < 8; d++) {
                o2[d][0] *= clo; o2[d][1] *= clo;
                o2[d][2] *= chi; o2[d][3] *= chi;
            }
        }

        // ---- O += P V (V row-major [j][d], ldsm.trans) ----
        const uint32_t vb = kvb + (uint32_t)(64 * AQS) * 2u;
#pragma unroll
        for (int ks = 0; ks < 4; ks++) {
            uint32_t a1f[4] = { p1h[2*ks][0], p1h[2*ks][1], p1h[2*ks+1][0], p1h[2*ks+1][1] };
            uint32_t a2f[4] = { p2h[2*ks][0], p2h[2*ks][1], p2h[2*ks+1][0], p2h[2*ks+1][1] };
            const uint32_t jrow = (uint32_t)(ks * 16 * AQS) * 2u;
#pragma unroll
            for (int dt2 = 0; dt2 < 4; dt2++) {
                uint32_t ra = sb + vb + v_base + jrow + (uint32_t)(dt2 * 16) * 2u;
                uint32_t vh[2][2];
                ldsm_x4_t(ra, vh[0][0], vh[0][1], vh[1][0], vh[1][1]);
#pragma unroll
                for (int q = 0; q < 2; q++) {
                    int dt = dt2 * 2 + q;
                    mma_f16(o1[dt], a1f, vh[q][0], vh[q][1]);
                    mma_f16(o2[dt], a2f, vh[q][0], vh[q][1]);
                }
            }
        }

        if (kt < 15) __syncthreads();   // protect buffer overwrite by next issue
    }

    // ---- epilogue: out = O1/l1 + O2/l2 (fp16) ----
    const float i1lo = 1.f / l1lo, i1hi = 1.f / l1hi;
    const float i2lo = 1.f / l2lo, i2hi = 1.f / l2hi;
    __half* obase = outp + (size_t)b * SEQ * C_DIM;
    const int r0 = q0 + wm + (lane >> 2);
    const int cb = hoff + (lane & 3) * 2;
#pragma unroll
    for (int dt = 0; dt < 8; dt++) {
        int col = cb + dt * 8;
        float v0 = o1[dt][0] * i1lo + o2[dt][0] * i2lo;
        float v1 = o1[dt][1] * i1lo + o2[dt][1] * i2lo;
        float v2 = o1[dt][2] * i1hi + o2[dt][2] * i2hi;
        float v3 = o1[dt][3] * i1hi + o2[dt][3] * i2hi;
        *(uint32_t*)(obase + (size_t)r0 * C_DIM + col) =
            pack_h2(__float2half_rn(v0), __float2half_rn(v1));
        *(uint32_t*)(obase + (size_t)(r0 + 8) * C_DIM + col) =
            pack_h2(__float2half_rn(v2), __float2half_rn(v3));
    }
}

// ============================================================
extern "C" void kernel_launch(void* const* d_in, const int* in_sizes, int n_in,
                              void* d_out, int out_size)
{
    const float* x      = (const float*)d_in[0];
    const float* y      = (const float*)d_in[1];
    const float* w_qkv  = (const float*)d_in[2];
    const float* w_proj = (const float*)d_in[3];
    const float* b_proj = (const float*)d_in[4];
    float* out = (float*)d_out;

    __half *xh, *yh, *wqh, *wph, *qxh, *qyh, *axh, *ayh;
    cudaGetSymbolAddress((void**)&xh,  g_x_h);
    cudaGetSymbolAddress((void**)&yh,  g_y_h);
    cudaGetSymbolAddress((void**)&wqh, g_wqkv_h);
    cudaGetSymbolAddress((void**)&wph, g_wproj_h);
    cudaGetSymbolAddress((void**)&qxh, g_qkvx_h);
    cudaGetSymbolAddress((void**)&qyh, g_qkvy_h);
    cudaGetSymbolAddress((void**)&axh, g_attx_h);
    cudaGetSymbolAddress((void**)&ayh, g_atty_h);

    cudaFuncSetAttribute(gemm_mma,
                         cudaFuncAttributeMaxDynamicSharedMemorySize, GEMM_SMEM);
    cudaFuncSetAttribute(attention_mma,
                         cudaFuncAttributeMaxDynamicSharedMemorySize, ATT_SMEM);

    // 0) fp32 -> fp16 converts (single fused launch, 4 float4/thread)
    const int nx = M_ROWS*C_DIM/4, nw = QKV_DIM*C_DIM/4, np = C_DIM*C_DIM/4;
    cvt4_kernel<<<(nx + nx + nw + np + 1023)/1024, 256>>>(
        x, xh, nx, y, yh, nx, w_qkv, wqh, nw, w_proj, wph, np);

    // 1) QKV projections, fp16 out, scale folded; y skips unused vy
    dim3 g1(QKV_DIM / 128, M_ROWS / 128, 2);
    gemm_mma<<<g1, 256, GEMM_SMEM>>>(xh, yh, wqh, nullptr,
                                     nullptr, nullptr, qxh, qyh,
                                     M_ROWS, QKV_DIM, C_DIM, 2304, 1);

    // 2) fused dual-softmax attention (pure fp16, scale pre-folded)
    attention_mma<<<dim3(SEQ / 128, HEADS * 2, BATCH), 256, ATT_SMEM>>>();

    // 3) output projections + bias, fp32 out
    dim3 g2(C_DIM / 128, M_ROWS / 128, 2);
    gemm_mma<<<g2, 256, GEMM_SMEM>>>(axh, ayh, wph, b_proj,
                                     out, out + (size_t)M_ROWS * C_DIM,
                                     nullptr, nullptr,
                                     M_ROWS, C_DIM, C_DIM, C_DIM, 0);
}

// round 16
// speedup vs baseline: 3.0452x; 1.0565x over previous
#include <cuda_runtime.h>
#include <cuda_fp16.h>
#include <cstdint>

#define C_DIM   768
#define QKV_DIM 3072
#define BATCH   4
#define SEQ     1024
#define HEADS   12
#define HD      64
#define M_ROWS  (BATCH*SEQ)   // 4096

// -------- scratch (allocation-free: device globals, all fp16) --------
__device__ __half g_x_h[M_ROWS*C_DIM];
__device__ __half g_y_h[M_ROWS*C_DIM];
__device__ __half g_wqkv_h[QKV_DIM*C_DIM];
__device__ __half g_wproj_h[C_DIM*C_DIM];
__device__ __half g_qkvx_h[M_ROWS*QKV_DIM];
__device__ __half g_qkvy_h[M_ROWS*QKV_DIM];
__device__ __half g_attx_h[M_ROWS*C_DIM];
__device__ __half g_atty_h[M_ROWS*C_DIM];

// ============================================================
// helpers
// ============================================================
__device__ __forceinline__ uint32_t smem_u32(const void* p) {
    uint32_t a;
    asm("{ .reg .u64 t; cvta.to.shared.u64 t, %1; cvt.u32.u64 %0, t; }"
        : "=r"(a) : "l"(p));
    return a;
}

__device__ __forceinline__ void ldsm_x4(uint32_t addr, uint32_t& r0, uint32_t& r1,
                                        uint32_t& r2, uint32_t& r3) {
    asm volatile("ldmatrix.sync.aligned.m8n8.x4.shared.b16 {%0,%1,%2,%3}, [%4];"
                 : "=r"(r0), "=r"(r1), "=r"(r2), "=r"(r3) : "r"(addr));
}

__device__ __forceinline__ void ldsm_x4_t(uint32_t addr, uint32_t& r0, uint32_t& r1,
                                          uint32_t& r2, uint32_t& r3) {
    asm volatile("ldmatrix.sync.aligned.m8n8.x4.trans.shared.b16 {%0,%1,%2,%3}, [%4];"
                 : "=r"(r0), "=r"(r1), "=r"(r2), "=r"(r3) : "r"(addr));
}

__device__ __forceinline__ void mma_f16(float* c, const uint32_t* a,
                                        uint32_t b0, uint32_t b1) {
    asm volatile(
        "mma.sync.aligned.m16n8k16.row.col.f32.f16.f16.f32 "
        "{%0,%1,%2,%3}, {%4,%5,%6,%7}, {%8,%9}, {%0,%1,%2,%3};"
        : "+f"(c[0]), "+f"(c[1]), "+f"(c[2]), "+f"(c[3])
        : "r"(a[0]), "r"(a[1]), "r"(a[2]), "r"(a[3]), "r"(b0), "r"(b1));
}

__device__ __forceinline__ void cp_async16(uint32_t saddr, const void* gptr) {
    asm volatile("cp.async.cg.shared.global [%0], [%1], 16;"
                 :: "r"(saddr), "l"(gptr));
}
__device__ __forceinline__ void cp_commit() {
    asm volatile("cp.async.commit_group;" ::: "memory");
}
__device__ __forceinline__ void cp_wait0() { asm volatile("cp.async.wait_group 0;" ::: "memory"); }
__device__ __forceinline__ void cp_wait1() { asm volatile("cp.async.wait_group 1;" ::: "memory"); }

__device__ __forceinline__ uint32_t pack_h2(__half a, __half b) {
    return ((uint32_t)__half_as_ushort(b) << 16) | (uint32_t)__half_as_ushort(a);
}

// fp32 float4 -> fp16 x4
__device__ __forceinline__ uint2 hi4h(float4 v) {
    return make_uint2(pack_h2(__float2half_rn(v.x), __float2half_rn(v.y)),
                      pack_h2(__float2half_rn(v.z), __float2half_rn(v.w)));
}

// ============================================================
// fused fp32 -> fp16 convert kernel (4 arrays, one launch, 4x ILP)
// ============================================================
__device__ __forceinline__ void cvt_one(
    int i,
    const float* __restrict__ s0, __half* __restrict__ d0, int n0,
    const float* __restrict__ s1, __half* __restrict__ d1, int n1,
    const float* __restrict__ s2, __half* __restrict__ d2, int n2,
    const float* __restrict__ s3, __half* __restrict__ d3, int n3)
{
    const float* s; __half* d;
    if (i < n0)                { s = s0; d = d0; }
    else if ((i -= n0) < n1)   { s = s1; d = d1; }
    else if ((i -= n1) < n2)   { s = s2; d = d2; }
    else if ((i -= n2) < n3)   { s = s3; d = d3; }
    else return;
    float4 v = ((const float4*)s)[i];
    ((uint2*)d)[i] = hi4h(v);
}

__global__ __launch_bounds__(256) void cvt4_kernel(
    const float* __restrict__ s0, __half* __restrict__ d0, int n0,
    const float* __restrict__ s1, __half* __restrict__ d1, int n1,
    const float* __restrict__ s2, __half* __restrict__ d2, int n2,
    const float* __restrict__ s3, __half* __restrict__ d3, int n3)
{
    int base = blockIdx.x * 1024 + threadIdx.x;
#pragma unroll
    for (int u = 0; u < 4; u++)
        cvt_one(base + u * 256, s0, d0, n0, s1, d1, n1, s2, d2, n2, s3, d3, n3);
}

// ============================================================
// fp16 mma.sync GEMM (fp32 accum). 1-pass.
// CTA tile 128m x 128n, 8 warps (2m x 4n), warp tile 64x32.
// BK=64 (64 MMAs/warp per stage), 3-deep cp.async ring, 1 sync/stage.
// smem 110592 B -> 2 CTAs/SM. qkv_scale folds +-hd^-0.5 into q chunks.
// ============================================================
#define LDH4 72                        // halves per row (64 + 8 pad)
#define ACH4 (128 * LDH4)              // 9216 halves per array (A or B)
#define STGB4 (2 * ACH4 * 2)           // 36864 bytes per stage
#define GEMM_SMEM (3 * STGB4)          // 110592 -> 2 CTAs/SM

__global__ __launch_bounds__(256, 2) void gemm_mma(
    const __half* __restrict__ A0, const __half* __restrict__ A1,
    const __half* __restrict__ B,
    const float* __restrict__ bias,
    float* __restrict__ Cf0, float* __restrict__ Cf1,
    __half* __restrict__ Ch0, __half* __restrict__ Ch1,
    int M, int N, int K, int n_lim1, int qkv_scale)
{
    extern __shared__ __align__(16) __half sh[];
    const int tid  = threadIdx.x;
    const int wid  = tid >> 5;
    const int lane = tid & 31;
    const int m0 = blockIdx.y * 128, n0 = blockIdx.x * 128;
    if (blockIdx.z && n0 >= n_lim1) return;   // vy skip for y-QKV
    const int wm = (wid & 1) * 64;
    const int wn = (wid >> 1) * 32;
    const int S  = K / 64;

    const __half* A = blockIdx.z ? A1 : A0;

    const uint32_t sbase = smem_u32(sh);

    auto issue_stage = [&](int s, int buf) {
        const int kb = s * 64;
        const uint32_t so = sbase + (uint32_t)buf * STGB4;
#pragma unroll
        for (int j = 0; j < 4; j++) {
            int cid = tid + j * 256;             // 0..1023
            int row = cid >> 3;                  // 0..127
            int c8  = (cid & 7) << 3;            // 0..56 halves
            cp_async16(so + (uint32_t)(row * LDH4 + c8) * 2u,
                       A + (size_t)(m0 + row) * K + kb + c8);
            cp_async16(so + (uint32_t)(ACH4 + row * LDH4 + c8) * 2u,
                       B + (size_t)(n0 + row) * K + kb + c8);
        }
    };

    float acc[4][4][4];
#pragma unroll
    for (int i = 0; i < 4; i++)
#pragma unroll
        for (int j = 0; j < 4; j++)
#pragma unroll
            for (int r = 0; r < 4; r++) acc[i][j][r] = 0.f;

    const int a_off = (wm + (lane & 15)) * LDH4 + ((lane >> 4) << 3);
    const int b_off = (wn + ((lane >> 4) << 3) + (lane & 7)) * LDH4 + (((lane >> 3) & 1) << 3);

    issue_stage(0, 0); cp_commit();
    issue_stage(1, 1); cp_commit();

    int buf = 0;
    for (int s = 0; s < S; s++) {
        if (s + 1 < S) cp_wait1();
        else           cp_wait0();
        __syncthreads();
        if (s + 2 < S) {
            int nb = buf + 2; if (nb >= 3) nb -= 3;
            issue_stage(s + 2, nb);
            cp_commit();
        }

        const uint32_t stg = sbase + (uint32_t)buf * STGB4;

#pragma unroll
        for (int ks = 0; ks < 4; ks++) {
            const uint32_t kofs = (uint32_t)(ks * 16) * 2u;
            uint32_t ah[4][4], bh[4][2];
#pragma unroll
            for (int mt = 0; mt < 4; mt++)
                ldsm_x4(stg + kofs + (uint32_t)(a_off + mt * 16 * LDH4) * 2u,
                        ah[mt][0], ah[mt][1], ah[mt][2], ah[mt][3]);
#pragma unroll
            for (int p = 0; p < 2; p++)
                ldsm_x4(stg + kofs + (uint32_t)(ACH4 + b_off + p * 16 * LDH4) * 2u,
                        bh[p*2][0], bh[p*2][1], bh[p*2+1][0], bh[p*2+1][1]);

#pragma unroll
            for (int mt = 0; mt < 4; mt++)
#pragma unroll
                for (int nt = 0; nt < 4; nt++)
                    mma_f16(acc[mt][nt], ah[mt], bh[nt][0], bh[nt][1]);
        }
        if (++buf == 3) buf = 0;
    }

    // ---- epilogue ----
    if (Cf0) {
        float* C = blockIdx.z ? Cf1 : Cf0;
#pragma unroll
        for (int mt = 0; mt < 4; mt++) {
            int row0 = m0 + wm + mt * 16 + (lane >> 2);
#pragma unroll
            for (int nt = 0; nt < 4; nt++) {
                int col = n0 + wn + nt * 8 + (lane & 3) * 2;
                float b0 = 0.f, b1 = 0.f;
                if (bias) { b0 = __ldg(bias + col); b1 = __ldg(bias + col + 1); }
                float2 v0 = make_float2(acc[mt][nt][0] + b0, acc[mt][nt][1] + b1);
                float2 v1 = make_float2(acc[mt][nt][2] + b0, acc[mt][nt][3] + b1);
                *(float2*)(C + (size_t)row0 * N + col)       = v0;
                *(float2*)(C + (size_t)(row0 + 8) * N + col) = v1;
            }
        }
    } else {
        // fold attention scale into q/qo chunks (tile-uniform: 128 | 768)
        float sc = 1.f;
        if (qkv_scale) sc = (n0 < 768) ? -0.125f : (n0 < 1536 ? 0.125f : 1.f);
        __half* C = blockIdx.z ? Ch1 : Ch0;
#pragma unroll
        for (int mt = 0; mt < 4; mt++) {
            int row0 = m0 + wm + mt * 16 + (lane >> 2);
#pragma unroll
            for (int nt = 0; nt < 4; nt++) {
                int col = n0 + wn + nt * 8 + (lane & 3) * 2;
                *(uint32_t*)(C + (size_t)row0 * N + col) =
                    pack_h2(__float2half_rn(acc[mt][nt][0] * sc),
                            __float2half_rn(acc[mt][nt][1] * sc));
                *(uint32_t*)(C + (size_t)(row0 + 8) * N + col) =
                    pack_h2(__float2half_rn(acc[mt][nt][2] * sc),
                            __float2half_rn(acc[mt][nt][3] * sc));
            }
        }
    }
}

// ============================================================
// Dual-softmax flash attention, pure fp16 operands (fp32 accum).
// Q pre-scaled (+-hd^-0.5) by the QKV epilogue.
// Q/K/V via cp.async; V row-major [j][d], fragments via ldsm.trans.
// ATT_SMEM padded above 116736 B to force 1 CTA/SM (R9 lesson).
// (measured at the ~270 TF/s mma.sync wall -- unchanged)
// ============================================================
#define AQS 72
#define OQ1 0
#define OQ2 (128*AQS)
#define OKV (2*128*AQS)
#define KVB (2*64*AQS)                  // per buffer: K, V
#define ATT_SMEM 117760                 // padded: > 233472/2 -> 1 CTA/SM

__global__ __launch_bounds__(256, 1) void attention_mma()
{
    extern __shared__ __align__(16) __half sh[];
    const uint32_t sb = smem_u32(sh);
    const int tid  = threadIdx.x;
    const int wid  = tid >> 5;
    const int lane = tid & 31;
    const int wm   = wid * 16;

    const int b    = blockIdx.z;
    const int h    = blockIdx.y >> 1;
    const int pair = blockIdx.y & 1;
    const int q0   = blockIdx.x * 128;
    const int hoff = h * HD;

    const __half* bx = g_qkvx_h + (size_t)b * SEQ * QKV_DIM;
    const __half* by = g_qkvy_h + (size_t)b * SEQ * QKV_DIM;

    const __half *Q1src, *Q2src, *Ksrc;
    __half* outp;
    if (pair == 0) { Q1src = bx + C_DIM; Q2src = by;  Ksrc = bx + 2 * C_DIM; outp = g_attx_h; }
    else           { Q1src = by + C_DIM; Q2src = bx;  Ksrc = by + 2 * C_DIM; outp = g_atty_h; }
    const __half* Vsrc = bx + 3 * C_DIM;   // vy = vx in the reference
    Q1src += hoff; Q2src += hoff; Ksrc += hoff; Vsrc += hoff;

    // ---- issue Q tiles (one-time, 8 cp.async/thread) ----
    {
        const __half* qs[2] = { Q1src, Q2src };
#pragma unroll
        for (int a = 0; a < 2; a++)
#pragma unroll
            for (int j = 0; j < 4; j++) {
                int cid = tid + j * 256;         // 0..1023
                int row = cid >> 3;              // 0..127
                int c8  = (cid & 7) << 3;        // 0..56
                cp_async16(sb + (uint32_t)(a * 128 * AQS + row * AQS + c8) * 2u,
                           qs[a] + (size_t)(q0 + row) * QKV_DIM + c8);
            }
    }

    // KV tile: 64 rows x 64 halves per tensor -> 512 slots -> 2/thread/tensor
    auto issue_kv = [&](int kt, int buf) {
        const int j0 = kt * 64;
        const int nb = OKV + buf * KVB;
#pragma unroll
        for (int j = 0; j < 2; j++) {
            int cid = tid + j * 256;             // 0..511
            int row = cid >> 3;                  // 0..63
            int c8  = (cid & 7) << 3;            // 0..56
            cp_async16(sb + (uint32_t)(nb + row * AQS + c8) * 2u,
                       Ksrc + (size_t)(j0 + row) * QKV_DIM + c8);
            cp_async16(sb + (uint32_t)(nb + 64 * AQS + row * AQS + c8) * 2u,
                       Vsrc + (size_t)(j0 + row) * QKV_DIM + c8);
        }
    };

    issue_kv(0, 0);
    cp_commit();   // group 0: Q + KV tile 0

    float o1[8][4], o2[8][4];
#pragma unroll
    for (int d = 0; d < 8; d++)
#pragma unroll
        for (int r = 0; r < 4; r++) { o1[d][r] = 0.f; o2[d][r] = 0.f; }
    float m1lo = -1e30f, m1hi = -1e30f, l1lo = 0.f, l1hi = 0.f;
    float m2lo = -1e30f, m2hi = -1e30f, l2lo = 0.f, l2hi = 0.f;

    const uint32_t a_base = (uint32_t)((wm + (lane & 15)) * AQS + ((lane >> 4) << 3)) * 2u;
    const uint32_t b_base = (uint32_t)((((lane >> 4) << 3) + (lane & 7)) * AQS
                                       + (((lane >> 3) & 1) << 3)) * 2u;
    const uint32_t v_base = (uint32_t)(((((lane >> 3) & 1) << 3) + (lane & 7)) * AQS
                                       + ((lane >> 4) << 3)) * 2u;

    for (int kt = 0; kt < 16; kt++) {
        const uint32_t kvb = (uint32_t)(OKV + (kt & 1) * KVB) * 2u;

        if (kt < 15) { issue_kv(kt + 1, (kt + 1) & 1); cp_commit(); cp_wait1(); }
        else         { cp_wait0(); }
        __syncthreads();

        // ---- S = Q K^T (fp16 x fp16 -> fp32; scale pre-folded) ----
        float s1[8][4], s2[8][4];
#pragma unroll
        for (int n = 0; n < 8; n++)
#pragma unroll
            for (int r = 0; r < 4; r++) { s1[n][r] = 0.f; s2[n][r] = 0.f; }

#pragma unroll
        for (int ks = 0; ks < 4; ks++) {
            const uint32_t kofs = (uint32_t)(ks * 16) * 2u;
            uint32_t a1h[4], a2h[4];
            ldsm_x4(sb + (uint32_t)(OQ1*2) + a_base + kofs, a1h[0], a1h[1], a1h[2], a1h[3]);
            ldsm_x4(sb + (uint32_t)(OQ2*2) + a_base + kofs, a2h[0], a2h[1], a2h[2], a2h[3]);
#pragma unroll
            for (int jt = 0; jt < 4; jt++) {
                uint32_t rb = sb + kvb + b_base + (uint32_t)(jt * 16 * AQS) * 2u + kofs;
                uint32_t bh[2][2];
                ldsm_x4(rb, bh[0][0], bh[0][1], bh[1][0], bh[1][1]);
#pragma unroll
                for (int q = 0; q < 2; q++) {
                    int nt = jt * 2 + q;
                    mma_f16(s1[nt], a1h, bh[q][0], bh[q][1]);
                    mma_f16(s2[nt], a2h, bh[q][0], bh[q][1]);
                }
            }
        }

        // ---- online softmax (per stream), P as fp16 ----
        uint32_t p1h[8][2], p2h[8][2];
        {
            float mxlo = -1e30f, mxhi = -1e30f;
#pragma unroll
            for (int n = 0; n < 8; n++) {
                mxlo = fmaxf(mxlo, fmaxf(s1[n][0], s1[n][1]));
                mxhi = fmaxf(mxhi, fmaxf(s1[n][2], s1[n][3]));
            }
            mxlo = fmaxf(mxlo, __shfl_xor_sync(0xffffffffu, mxlo, 1));
            mxlo = fmaxf(mxlo, __shfl_xor_sync(0xffffffffu, mxlo, 2));
            mxhi = fmaxf(mxhi, __shfl_xor_sync(0xffffffffu, mxhi, 1));
            mxhi = fmaxf(mxhi, __shfl_xor_sync(0xffffffffu, mxhi, 2));
            float mnlo = fmaxf(m1lo, mxlo), mnhi = fmaxf(m1hi, mxhi);
            float clo = __expf(m1lo - mnlo), chi = __expf(m1hi - mnhi);
            m1lo = mnlo; m1hi = mnhi;
            float sl = 0.f, shh = 0.f;
#pragma unroll
            for (int n = 0; n < 8; n++) {
                float p0 = __expf(s1[n][0] - mnlo);
                float p1 = __expf(s1[n][1] - mnlo);
                float p2 = __expf(s1[n][2] - mnhi);
                float p3 = __expf(s1[n][3] - mnhi);
                sl += p0 + p1; shh += p2 + p3;
                p1h[n][0] = pack_h2(__float2half_rn(p0), __float2half_rn(p1));
                p1h[n][1] = pack_h2(__float2half_rn(p2), __float2half_rn(p3));
            }
            sl  += __shfl_xor_sync(0xffffffffu, sl, 1);
            sl  += __shfl_xor_sync(0xffffffffu, sl, 2);
            shh += __shfl_xor_sync(0xffffffffu, shh, 1);
            shh += __shfl_xor_sync(0xffffffffu, shh, 2);
            l1lo = l1lo * clo + sl; l1hi = l1hi * chi + shh;
#pragma unroll
            for (int d = 0; d < 8; d++) {
                o1[d][0] *= clo; o1[d][1] *= clo;
                o1[d][2] *= chi; o1[d][3] *= chi;
            }
        }
        {
            float mxlo = -1e30f, mxhi = -1e30f;
#pragma unroll
            for (int n = 0; n < 8; n++) {
                mxlo = fmaxf(mxlo, fmaxf(s2[n][0], s2[n][1]));
                mxhi = fmaxf(mxhi, fmaxf(s2[n][2], s2[n][3]));
            }
            mxlo = fmaxf(mxlo, __shfl_xor_sync(0xffffffffu, mxlo, 1));
            mxlo = fmaxf(mxlo, __shfl_xor_sync(0xffffffffu, mxlo, 2));
            mxhi = fmaxf(mxhi, __shfl_xor_sync(0xffffffffu, mxhi, 1));
            mxhi = fmaxf(mxhi, __shfl_xor_sync(0xffffffffu, mxhi, 2));
            float mnlo = fmaxf(m2lo, mxlo), mnhi = fmaxf(m2hi, mxhi);
            float clo = __expf(m2lo - mnlo), chi = __expf(m2hi - mnhi);
            m2lo = mnlo; m2hi = mnhi;
            float sl = 0.f, shh = 0.f;
#pragma unroll
            for (int n = 0; n < 8; n++) {
                float p0 = __expf(s2[n][0] - mnlo);
                float p1 = __expf(s2[n][1] - mnlo);
                float p2 = __expf(s2[n][2] - mnhi);
                float p3 = __expf(s2[n][3] - mnhi);
                sl += p0 + p1; shh += p2 + p3;
                p2h[n][0] = pack_h2(__float2half_rn(p0), __float2half_rn(p1));
                p2h[n][1] = pack_h2(__float2half_rn(p2), __float2half_rn(p3));
            }
            sl  += __shfl_xor_sync(0xffffffffu, sl, 1);
            sl  += __shfl_xor_sync(0xffffffffu, sl, 2);
            shh += __shfl_xor_sync(0xffffffffu, shh, 1);
            shh += __shfl_xor_sync(0xffffffffu, shh, 2);
            l2lo = l2lo * clo + sl; l2hi = l2hi * chi + shh;
#pragma unroll
            for (int d = 0; d < 8; d++) {
                o2[d][0] *= clo; o2[d][1] *= clo;
                o2[d][2] *= chi; o2[d][3] *= chi;
            }
        }

        // ---- O += P V (V row-major [j][d], ldsm.trans) ----
        const uint32_t vb = kvb + (uint32_t)(64 * AQS) * 2u;
#pragma unroll
        for (int ks = 0; ks < 4; ks++) {
            uint32_t a1f[4] = { p1h[2*ks][0], p1h[2*ks][1], p1h[2*ks+1][0], p1h[2*ks+1][1] };
            uint32_t a2f[4] = { p2h[2*ks][0], p2h[2*ks][1], p2h[2*ks+1][0], p2h[2*ks+1][1] };
            const uint32_t jrow = (uint32_t)(ks * 16 * AQS) * 2u;
#pragma unroll
            for (int dt2 = 0; dt2 < 4; dt2++) {
                uint32_t ra = sb + vb + v_base + jrow + (uint32_t)(dt2 * 16) * 2u;
                uint32_t vh[2][2];
                ldsm_x4_t(ra, vh[0][0], vh[0][1], vh[1][0], vh[1][1]);
#pragma unroll
                for (int q = 0; q < 2; q++) {
                    int dt = dt2 * 2 + q;
                    mma_f16(o1[dt], a1f, vh[q][0], vh[q][1]);
                    mma_f16(o2[dt], a2f, vh[q][0], vh[q][1]);
                }
            }
        }

        if (kt < 15) __syncthreads();   // protect buffer overwrite by next issue
    }

    // ---- epilogue: out = O1/l1 + O2/l2 (fp16) ----
    const float i1lo = 1.f / l1lo, i1hi = 1.f / l1hi;
    const float i2lo = 1.f / l2lo, i2hi = 1.f / l2hi;
    __half* obase = outp + (size_t)b * SEQ * C_DIM;
    const int r0 = q0 + wm + (lane >> 2);
    const int cb = hoff + (lane & 3) * 2;
#pragma unroll
    for (int dt = 0; dt < 8; dt++) {
        int col = cb + dt * 8;
        float v0 = o1[dt][0] * i1lo + o2[dt][0] * i2lo;
        float v1 = o1[dt][1] * i1lo + o2[dt][1] * i2lo;
        float v2 = o1[dt][2] * i1hi + o2[dt][2] * i2hi;
        float v3 = o1[dt][3] * i1hi + o2[dt][3] * i2hi;
        *(uint32_t*)(obase + (size_t)r0 * C_DIM + col) =
            pack_h2(__float2half_rn(v0), __float2half_rn(v1));
        *(uint32_t*)(obase + (size_t)(r0 + 8) * C_DIM + col) =
            pack_h2(__float2half_rn(v2), __float2half_rn(v3));
    }
}

// ============================================================
extern "C" void kernel_launch(void* const* d_in, const int* in_sizes, int n_in,
                              void* d_out, int out_size)
{
    const float* x      = (const float*)d_in[0];
    const float* y      = (const float*)d_in[1];
    const float* w_qkv  = (const float*)d_in[2];
    const float* w_proj = (const float*)d_in[3];
    const float* b_proj = (const float*)d_in[4];
    float* out = (float*)d_out;

    __half *xh, *yh, *wqh, *wph, *qxh, *qyh, *axh, *ayh;
    cudaGetSymbolAddress((void**)&xh,  g_x_h);
    cudaGetSymbolAddress((void**)&yh,  g_y_h);
    cudaGetSymbolAddress((void**)&wqh, g_wqkv_h);
    cudaGetSymbolAddress((void**)&wph, g_wproj_h);
    cudaGetSymbolAddress((void**)&qxh, g_qkvx_h);
    cudaGetSymbolAddress((void**)&qyh, g_qkvy_h);
    cudaGetSymbolAddress((void**)&axh, g_attx_h);
    cudaGetSymbolAddress((void**)&ayh, g_atty_h);

    cudaFuncSetAttribute(gemm_mma,
                         cudaFuncAttributeMaxDynamicSharedMemorySize, GEMM_SMEM);
    cudaFuncSetAttribute(attention_mma,
                         cudaFuncAttributeMaxDynamicSharedMemorySize, ATT_SMEM);

    // 0) fp32 -> fp16 converts (single fused launch, 4 float4/thread)
    const int nx = M_ROWS*C_DIM/4, nw = QKV_DIM*C_DIM/4, np = C_DIM*C_DIM/4;
    cvt4_kernel<<<(nx + nx + nw + np + 1023)/1024, 256>>>(
        x, xh, nx, y, yh, nx, w_qkv, wqh, nw, w_proj, wph, np);

    // 1) QKV projections, fp16 out, scale folded; y skips unused vy
    dim3 g1(QKV_DIM / 128, M_ROWS / 128, 2);
    gemm_mma<<<g1, 256, GEMM_SMEM>>>(xh, yh, wqh, nullptr,
                                     nullptr, nullptr, qxh, qyh,
                                     M_ROWS, QKV_DIM, C_DIM, 2304, 1);

    // 2) fused dual-softmax attention (pure fp16, scale pre-folded)
    attention_mma<<<dim3(SEQ / 128, HEADS * 2, BATCH), 256, ATT_SMEM>>>();

    // 3) output projections + bias, fp32 out
    dim3 g2(C_DIM / 128, M_ROWS / 128, 2);
    gemm_mma<<<g2, 256, GEMM_SMEM>>>(axh, ayh, wph, b_proj,
                                     out, out + (size_t)M_ROWS * C_DIM,
                                     nullptr, nullptr,
                                     M_ROWS, C_DIM, C_DIM, C_DIM, 0);
}